// round 7
// baseline (speedup 1.0000x reference)
#include <cuda_runtime.h>
#include <cuda_fp16.h>
#include <cstdint>

// Problem constants
#define BATCH 8192
#define D_IN  1024
#define NH    2048
#define KLR   4
#define NCLS  1000
#define BN_EPS 1e-5f
#define NSEG  32

#define STAGES 3
#define STAGE_BYTES 49152           // A 16KB (128x128B) | B 32KB (256x128B)
#define SMEM_TOTAL (STAGES * STAGE_BYTES)

static __device__ __forceinline__ uint32_t smem_u32(const void* p) {
    uint32_t a;
    asm("{ .reg .u64 t; cvta.to.shared.u64 t, %1; cvt.u32.u64 %0, t; }" : "=r"(a) : "l"(p));
    return a;
}
static __device__ __forceinline__ void cp16(uint32_t dst, const void* src, uint32_t bytes) {
    asm volatile("cp.async.cg.shared.global [%0], [%1], 16, %2;" :: "r"(dst), "l"(src), "r"(bytes) : "memory");
}
#define CP_COMMIT() asm volatile("cp.async.commit_group;" ::: "memory")
#define CP_WAIT(n)  asm volatile("cp.async.wait_group %0;" :: "n"(n) : "memory")
#define LDSM4(r0, r1, r2, r3, a) \
    asm volatile("ldmatrix.sync.aligned.m8n8.x4.shared.b16 {%0,%1,%2,%3}, [%4];" \
        : "=r"(r0), "=r"(r1), "=r"(r2), "=r"(r3) : "r"(a))
#define MMA16816(c, a, b0, b1) \
    asm volatile("mma.sync.aligned.m16n8k16.row.col.f32.f16.f16.f32 " \
        "{%0,%1,%2,%3},{%4,%5,%6,%7},{%8,%9},{%0,%1,%2,%3};" \
        : "+f"((c)[0]), "+f"((c)[1]), "+f"((c)[2]), "+f"((c)[3]) \
        : "r"((a)[0]), "r"((a)[1]), "r"((a)[2]), "r"((a)[3]), "r"(b0), "r"(b1))

// ---------------- static device scratch ----------------
__device__ float g_S[(size_t)BATCH * NH];
__device__ float g_Pq[(size_t)BATCH * NH];         // fused proj^2 sums
__device__ float g_t[(size_t)BATCH * NH];
__device__ __align__(1024) __half g_a2x[(size_t)BATCH * 2 * D_IN];        // x    [hi|lo] fp16
__device__ __align__(1024) __half g_a2f[(size_t)BATCH * 2 * NH];          // feat [hi|lo] fp16
__device__ __align__(1024) __half g_b1[(size_t)(NH * KLR + NH) * NH];     // [v | mu] rows, hi fp16
__device__ __align__(1024) __half g_b1l[(size_t)NCLS * NH];               // Wl hi fp16
__device__ float g_rowsq[BATCH];
__device__ float g_msq[NH];
__device__ float g_c[NH * KLR];
__device__ float g_scale[NH];
__device__ float g_shift[NH];
__device__ double g_psum[NSEG * NH];
__device__ double g_psq[NSEG * NH];

// ================= HMMA fp16 2-term split GEMM (128x256 tile, 512 thr) =================
// Logical C[m,n] = hiA*hiB + loA*hiB  (A carries ~22 mantissa bits).
// A2 (M, 2*Kd) = [hi|lo] fp16, B1 (Nrows, Kd) = hi fp16.
// Output: col < Ncut  -> proj^2 4-group reduction: Pq[m*NqW + col/4] = sum_4 (C-c)^2
//         col >= Ncut -> Cs[m*Ns + (col-Ncut)] (+bias)
__global__ void __launch_bounds__(512)
gemm_mma(const __half* __restrict__ A2, const __half* __restrict__ B1,
         float* __restrict__ Pq, float* __restrict__ Cs, const float* __restrict__ cvec,
         int Mt, int Ncut, int Ntot, int Ns, int NqW, int Kd, const float* __restrict__ bias)
{
    extern __shared__ __align__(1024) char smem[];
    const uint32_t sbase = smem_u32(smem);
    const int tid = threadIdx.x;
    const int wid = tid >> 5;
    const int lane = tid & 31;
    const int wm = wid >> 2;          // 0..3  (m-warp, 32 rows)
    const int wn = wid & 3;           // 0..3  (n-warp, 64 cols)

    // banded raster: 8 n-tiles per band, n-fast within band
    const int nt_total = (Ntot + 255) >> 8;
    const int bw0 = 8;
    const int per_band = Mt * bw0;
    const int band = blockIdx.x / per_band;
    const int rem = blockIdx.x % per_band;
    int nb = nt_total - band * bw0; if (nb > bw0) nb = bw0;
    const int mtile = rem / nb;
    const int ntile = band * bw0 + rem % nb;
    const int row0 = mtile * 128;
    const int col0 = ntile * 256;
    const int nk1 = Kd >> 6;
    const int nk = 2 * nk1;
    const int Kd2 = 2 * Kd;

    float acc[2][8][4];
#pragma unroll
    for (int i = 0; i < 2; i++)
#pragma unroll
        for (int j = 0; j < 8; j++)
#pragma unroll
            for (int r = 0; r < 4; r++) acc[i][j][r] = 0.f;

    const int aRow = wm * 32 + (lane & 15);
    const int aK8 = (lane >> 4) * 8;
    const int bRowBase = wn * 64 + (lane & 7) + ((lane >> 4) & 1) * 8;
    const int bK8 = ((lane >> 3) & 1) * 8;

    auto issue = [&](int i) {
        if (i < nk) {
            const int s = i % STAGES;
            const uint32_t stA = sbase + s * STAGE_BYTES;
            const uint32_t stB = stA + 16384;
            const int ib = (i >= nk1) ? i - nk1 : i;
            const __half* Ab = A2 + (size_t)row0 * Kd2 + (i << 6);
            const __half* Bb = B1 + (ib << 6);
#pragma unroll
            for (int it = 0; it < 2; it++) {
                int id = it * 512 + tid;
                int row = id >> 3, c = id & 7;
                uint32_t off = (uint32_t)(row * 128 + ((c * 16) ^ ((row & 7) << 4)));
                cp16(stA + off, Ab + (size_t)row * Kd2 + c * 8, 16);
            }
#pragma unroll
            for (int it = 0; it < 4; it++) {
                int id = it * 512 + tid;
                int row = id >> 3, c = id & 7;
                int gn = col0 + row;
                uint32_t bytes = (gn < Ntot) ? 16u : 0u;
                if (gn >= Ntot) gn = col0;
                uint32_t off = (uint32_t)(row * 128 + ((c * 16) ^ ((row & 7) << 4)));
                cp16(stB + off, Bb + (size_t)gn * Kd + c * 8, bytes);
            }
        }
        CP_COMMIT();
    };

#pragma unroll
    for (int i = 0; i < STAGES - 1; i++) issue(i);

    for (int i = 0; i < nk; i++) {
        CP_WAIT(STAGES - 2);
        __syncthreads();
        const int s = i % STAGES;
        const uint32_t stA = sbase + s * STAGE_BYTES;
        const uint32_t stB = stA + 16384;
#pragma unroll
        for (int ks = 0; ks < 4; ks++) {
            uint32_t a[2][4], b[4][4];
            const int kc = ks * 16;
#pragma unroll
            for (int mi = 0; mi < 2; mi++) {
                int row = aRow + mi * 16;
                uint32_t off = (uint32_t)(row * 128 + (((kc + aK8) * 2) ^ ((row & 7) << 4)));
                LDSM4(a[mi][0], a[mi][1], a[mi][2], a[mi][3], stA + off);
            }
#pragma unroll
            for (int nbk = 0; nbk < 4; nbk++) {
                int row = bRowBase + nbk * 16;
                uint32_t off = (uint32_t)(row * 128 + (((kc + bK8) * 2) ^ ((row & 7) << 4)));
                LDSM4(b[nbk][0], b[nbk][1], b[nbk][2], b[nbk][3], stB + off);
            }
#pragma unroll
            for (int mi = 0; mi < 2; mi++)
#pragma unroll
                for (int ni = 0; ni < 8; ni++)
                    MMA16816(acc[mi][ni], a[mi], b[ni >> 1][(ni & 1) * 2], b[ni >> 1][(ni & 1) * 2 + 1]);
        }
        issue(i + STAGES - 1);
    }

    // ---- epilogue ----
#pragma unroll
    for (int mi = 0; mi < 2; mi++) {
        const int m = row0 + wm * 32 + mi * 16 + (lane >> 2);
#pragma unroll
        for (int ni = 0; ni < 8; ni++) {
            const int col = col0 + wn * 64 + ni * 8 + (lane & 3) * 2;
            float2 v0 = make_float2(acc[mi][ni][0], acc[mi][ni][1]);
            float2 v1 = make_float2(acc[mi][ni][2], acc[mi][ni][3]);
            if (col < Ncut) {
                // proj^2 reduction over 4-col groups: (p - c)^2, pairwise shuffle
                float c0 = cvec[col], c1 = cvec[col + 1];
                float d00 = v0.x - c0, d01 = v0.y - c1;
                float d10 = v1.x - c0, d11 = v1.y - c1;
                float dd0 = d00 * d00 + d01 * d01;
                float dd1 = d10 * d10 + d11 * d11;
                float q0 = dd0 + __shfl_xor_sync(0xffffffffu, dd0, 1);
                float q1 = dd1 + __shfl_xor_sync(0xffffffffu, dd1, 1);
                if ((lane & 1) == 0) {
                    int g = col >> 2;
                    Pq[(size_t)m * NqW + g] = q0;
                    Pq[(size_t)(m + 8) * NqW + g] = q1;
                }
            } else {
                int sc = col - Ncut;
                if (sc < Ns) {
                    if (bias) {
                        float b0 = bias[sc], b1 = bias[sc + 1];
                        v0.x += b0; v0.y += b1; v1.x += b0; v1.y += b1;
                    }
                    *(float2*)(Cs + (size_t)m * Ns + sc) = v0;
                    *(float2*)(Cs + (size_t)(m + 8) * Ns + sc) = v1;
                }
            }
        }
    }
}

// ---------------- split: fp32 -> [hi | lo] fp16 per row (A operands) ----------------
__global__ void split2(const float* __restrict__ src, __half* __restrict__ dst, int D) {
    size_t i = (size_t)blockIdx.x * 256 + threadIdx.x;
    size_t r = i / (size_t)D;
    int d = (int)(i - r * D);
    float x = src[i];
    __half h = __float2half(x);
    __half l = __float2half(x - __half2float(h));
    __half* o = dst + r * (size_t)(2 * D);
    o[d] = h; o[D + d] = l;
}

// ---------------- cast: fp32 -> fp16 (logits B) ----------------
__global__ void castB(const float* __restrict__ src, __half* __restrict__ dst) {
    size_t i = (size_t)blockIdx.x * 256 + threadIdx.x;
    dst[i] = __float2half(src[i]);
}

// ---------------- row sum of squares (fp32 source) ----------------
__global__ void rowsq_kernel(const float* __restrict__ x, float* __restrict__ out, int D) {
    int b = blockIdx.x;
    const float* p = x + (size_t)b * D;
    float s = 0.f;
    for (int i = threadIdx.x; i < D; i += 256) { float v = p[i]; s = fmaf(v, v, s); }
    __shared__ float red[256];
    red[threadIdx.x] = s;
    __syncthreads();
    for (int off = 128; off > 0; off >>= 1) {
        if (threadIdx.x < off) red[threadIdx.x] += red[threadIdx.x + off];
        __syncthreads();
    }
    if (threadIdx.x == 0) out[b] = red[0];
}

// ---------------- row sum of squares from [hi|lo] fp16 split rows ----------------
__global__ void rowsq_split(const __half* __restrict__ f2, float* __restrict__ out, int D) {
    int b = blockIdx.x;
    const __half* p = f2 + (size_t)b * 2 * D;
    float s = 0.f;
    for (int i = threadIdx.x; i < D; i += 256) {
        float v = __half2float(p[i]) + __half2float(p[D + i]);
        s = fmaf(v, v, s);
    }
    __shared__ float red[256];
    red[threadIdx.x] = s;
    __syncthreads();
    for (int off = 128; off > 0; off >>= 1) {
        if (threadIdx.x < off) red[threadIdx.x] += red[threadIdx.x + off];
        __syncthreads();
    }
    if (threadIdx.x == 0) out[b] = red[0];
}

// ------- fused prep + cast: msq, c, and fp16 [v|mu] rows in one pass -------
// block n: reads mu row + 4 v rows (fp32), writes their fp16 copies into B1
// (v rows at n*KLR+k, mu row at NH*KLR+n), computes msq[n] and c[n][k].
__global__ void prep_cast(const float* __restrict__ mu, const float* __restrict__ v,
                          __half* __restrict__ B1,
                          float* __restrict__ msq, float* __restrict__ c, int D) {
    int n = blockIdx.x;
    const float* mp = mu + (size_t)n * D;
    const float* vp = v + (size_t)n * KLR * D;
    __half* bmu = B1 + ((size_t)(NH * KLR) + n) * D;
    __half* bv  = B1 + (size_t)n * KLR * D;
    float acc[5] = {0.f, 0.f, 0.f, 0.f, 0.f};
    for (int i = threadIdx.x; i < D; i += 256) {
        float m = mp[i];
        bmu[i] = __float2half(m);
        acc[0] = fmaf(m, m, acc[0]);
#pragma unroll
        for (int k = 0; k < KLR; k++) {
            float vv = vp[(size_t)k * D + i];
            bv[(size_t)k * D + i] = __float2half(vv);
            acc[k + 1] = fmaf(m, vv, acc[k + 1]);
        }
    }
    __shared__ float red[256];
    for (int j = 0; j < 5; j++) {
        red[threadIdx.x] = acc[j];
        __syncthreads();
        for (int off = 128; off > 0; off >>= 1) {
            if (threadIdx.x < off) red[threadIdx.x] += red[threadIdx.x + off];
            __syncthreads();
        }
        if (threadIdx.x == 0) {
            if (j == 0) msq[n] = red[0];
            else        c[n * KLR + (j - 1)] = red[0];
        }
        __syncthreads();
    }
}

// ------- fused quad epilogue + single-pass fp64 BN statistics -------
__global__ void quad_bnsum(const float* __restrict__ S, const float* __restrict__ Pq,
                           const float* __restrict__ rsq, const float* __restrict__ msq,
                           const float* __restrict__ lam,
                           float* __restrict__ t, double* __restrict__ psum,
                           double* __restrict__ psq, int mode) {
    int n = blockIdx.x * 256 + threadIdx.x;
    int seg = blockIdx.y;
    const int rows = BATCH / NSEG;
    float lamn = lam[n];
    float msqn = msq[n];
    double s = 0.0, s2 = 0.0;
    size_t b0 = (size_t)seg * rows;
    for (int r = 0; r < rows; r++) {
        size_t b = b0 + r;
        size_t idx = b * NH + n;
        float q = lamn * (rsq[b] - 2.f * S[idx] + msqn) + Pq[idx];
        float v = mode ? expf(-q * (1.0f / (float)NH)) : -q;
        t[idx] = v;
        double dv = (double)v;
        s += dv;
        s2 = fma(dv, dv, s2);
    }
    psum[seg * NH + n] = s;
    psq[seg * NH + n] = s2;
}

// ------- BN finalize: combine partials, exact var = E[x^2]-m^2 in fp64 -------
__global__ void bn_stats(const double* __restrict__ psum, const double* __restrict__ psq,
                         const float* __restrict__ g, const float* __restrict__ be,
                         float* __restrict__ scale, float* __restrict__ shift) {
    int n = blockIdx.x * 256 + threadIdx.x;
    double s = 0.0, s2 = 0.0;
    for (int i = 0; i < NSEG; i++) { s += psum[i * NH + n]; s2 += psq[i * NH + n]; }
    double mean = s * (1.0 / (double)BATCH);
    double var = s2 * (1.0 / (double)BATCH) - mean * mean;
    float rstd = (float)(1.0 / sqrt(var + (double)BN_EPS));
    float sc = g[n] * rstd;
    scale[n] = sc;
    shift[n] = be[n] - (float)mean * sc;
}

// applies BN (+optional relu), writes [hi|lo] fp16 pair rows + optional fp32 outputs
__global__ void bn_apply(const float* __restrict__ t, const float* __restrict__ scale,
                         const float* __restrict__ shift,
                         __half* __restrict__ f2,
                         float* o1, float* o2, int relu) {
    size_t idx = (size_t)blockIdx.x * 256 + threadIdx.x;
    int n = (int)(idx & (NH - 1));
    size_t b = idx >> 11;
    float v = fmaf(t[idx], scale[n], shift[n]);
    if (relu) v = fmaxf(v, 0.f);
    __half h = __float2half(v);
    __half l = __float2half(v - __half2float(h));
    __half* o = f2 + b * (size_t)(2 * NH);
    o[n] = h; o[NH + n] = l;
    if (o1) o1[idx] = v;
    if (o2) o2[idx] = v;
}

// ---------------- host orchestration ----------------
extern "C" void kernel_launch(void* const* d_in, const int* in_sizes, int n_in,
                              void* d_out, int out_size) {
    const float* x    = (const float*)d_in[0];
    const float* mu1  = (const float*)d_in[1];
    const float* lam1 = (const float*)d_in[2];
    const float* v1   = (const float*)d_in[3];
    const float* g1   = (const float*)d_in[4];
    const float* b1   = (const float*)d_in[5];
    const float* mu2  = (const float*)d_in[6];
    const float* lam2 = (const float*)d_in[7];
    const float* v2   = (const float*)d_in[8];
    const float* g2   = (const float*)d_in[9];
    const float* b2   = (const float*)d_in[10];
    const float* Wl   = (const float*)d_in[11];
    const float* bl   = (const float*)d_in[12];

    float *pS, *pPq, *pT, *pR, *pM, *pC, *pScale, *pShift;
    double *pPsum, *pPsq;
    __half *pA2x, *pA2f, *pB1, *pB1l;
    cudaGetSymbolAddress((void**)&pS, g_S);
    cudaGetSymbolAddress((void**)&pPq, g_Pq);
    cudaGetSymbolAddress((void**)&pT, g_t);
    cudaGetSymbolAddress((void**)&pA2x, g_a2x);
    cudaGetSymbolAddress((void**)&pA2f, g_a2f);
    cudaGetSymbolAddress((void**)&pB1, g_b1);
    cudaGetSymbolAddress((void**)&pB1l, g_b1l);
    cudaGetSymbolAddress((void**)&pR, g_rowsq);
    cudaGetSymbolAddress((void**)&pM, g_msq);
    cudaGetSymbolAddress((void**)&pC, g_c);
    cudaGetSymbolAddress((void**)&pScale, g_scale);
    cudaGetSymbolAddress((void**)&pShift, g_shift);
    cudaGetSymbolAddress((void**)&pPsum, g_psum);
    cudaGetSymbolAddress((void**)&pPsq, g_psq);

    cudaFuncSetAttribute(gemm_mma, cudaFuncAttributeMaxDynamicSharedMemorySize, SMEM_TOTAL);

    const size_t LOGITS_SZ = (size_t)BATCH * NCLS;
    const size_t FEAT_SZ   = (size_t)BATCH * NH;
    float* out = (float*)d_out;
    size_t extra = ((size_t)out_size > LOGITS_SZ) ? ((size_t)out_size - LOGITS_SZ) / FEAT_SZ : 0;
    float* f1dst = (extra >= 1) ? out + LOGITS_SZ : nullptr;
    float* f2a   = (extra >= 2) ? out + LOGITS_SZ + FEAT_SZ : nullptr;
    float* f2b   = (extra >= 3) ? out + LOGITS_SZ + 2 * FEAT_SZ : nullptr;

    dim3 bn_grid(NH / 256, NSEG);
    const int elem_blocks = (int)(((size_t)BATCH * NH) / 256);
    const int Mt = BATCH / 128;         // 64
    const int NMERGED = NH * (KLR + 1); // 10240
    const int merged_grid = Mt * (NMERGED / 256);  // 2560

    // ---------- Layer 1 ----------
    split2<<<(BATCH * D_IN) / 256, 256>>>(x, pA2x, D_IN);
    prep_cast<<<NH, 256>>>(mu1, v1, pB1, pM, pC, D_IN);
    rowsq_kernel<<<BATCH, 256>>>(x, pR, D_IN);
    gemm_mma<<<merged_grid, 512, SMEM_TOTAL>>>(pA2x, pB1, pPq, pS, pC, Mt, NH * KLR, NMERGED, NH, NH, D_IN, nullptr);
    quad_bnsum<<<bn_grid, 256>>>(pS, pPq, pR, pM, lam1, pT, pPsum, pPsq, 0);
    bn_stats<<<NH / 256, 256>>>(pPsum, pPsq, g1, b1, pScale, pShift);
    bn_apply<<<elem_blocks, 256>>>(pT, pScale, pShift, pA2f, f1dst, nullptr, 0);

    // ---------- Layer 2 ----------
    prep_cast<<<NH, 256>>>(mu2, v2, pB1, pM, pC, NH);
    rowsq_split<<<BATCH, 256>>>(pA2f, pR, NH);
    gemm_mma<<<merged_grid, 512, SMEM_TOTAL>>>(pA2f, pB1, pPq, pS, pC, Mt, NH * KLR, NMERGED, NH, NH, NH, nullptr);
    quad_bnsum<<<bn_grid, 256>>>(pS, pPq, pR, pM, lam2, pT, pPsum, pPsq, 1);
    bn_stats<<<NH / 256, 256>>>(pPsum, pPsq, g2, b2, pScale, pShift);
    bn_apply<<<elem_blocks, 256>>>(pT, pScale, pShift, pA2f, f2a, f2b, 1);

    // ---------- Logits ----------
    castB<<<(NCLS * NH) / 256, 256>>>(Wl, pB1l);
    gemm_mma<<<Mt * ((NCLS + 255) / 256), 512, SMEM_TOTAL>>>(pA2f, pB1l, nullptr, out, nullptr, Mt, 0, NCLS, NCLS, 0, NH, bl);
}

// round 8
// speedup vs baseline: 1.7852x; 1.7852x over previous
#include <cuda_runtime.h>
#include <cuda_fp16.h>
#include <cstdint>

// Problem constants
#define BATCH 8192
#define D_IN  1024
#define NH    2048
#define KLR   4
#define NCLS  1000
#define BN_EPS 1e-5f
#define NSEG  32

#define STAGES 3
#define STAGE_BYTES 32768           // A 16KB (128x128B) | B 16KB (128x128B)
#define SMEM_TOTAL (STAGES * STAGE_BYTES)

static __device__ __forceinline__ uint32_t smem_u32(const void* p) {
    uint32_t a;
    asm("{ .reg .u64 t; cvta.to.shared.u64 t, %1; cvt.u32.u64 %0, t; }" : "=r"(a) : "l"(p));
    return a;
}
static __device__ __forceinline__ void cp16(uint32_t dst, const void* src, uint32_t bytes) {
    asm volatile("cp.async.cg.shared.global [%0], [%1], 16, %2;" :: "r"(dst), "l"(src), "r"(bytes) : "memory");
}
#define CP_COMMIT() asm volatile("cp.async.commit_group;" ::: "memory")
#define CP_WAIT(n)  asm volatile("cp.async.wait_group %0;" :: "n"(n) : "memory")
#define LDSM4(r0, r1, r2, r3, a) \
    asm volatile("ldmatrix.sync.aligned.m8n8.x4.shared.b16 {%0,%1,%2,%3}, [%4];" \
        : "=r"(r0), "=r"(r1), "=r"(r2), "=r"(r3) : "r"(a))
#define MMA16816(c, a, b0, b1) \
    asm volatile("mma.sync.aligned.m16n8k16.row.col.f32.f16.f16.f32 " \
        "{%0,%1,%2,%3},{%4,%5,%6,%7},{%8,%9},{%0,%1,%2,%3};" \
        : "+f"((c)[0]), "+f"((c)[1]), "+f"((c)[2]), "+f"((c)[3]) \
        : "r"((a)[0]), "r"((a)[1]), "r"((a)[2]), "r"((a)[3]), "r"(b0), "r"(b1))

// ---------------- static device scratch ----------------
__device__ float g_S[(size_t)BATCH * NH];
__device__ float g_Pq[(size_t)BATCH * NH];         // fused proj^2 sums
__device__ float g_t[(size_t)BATCH * NH];
__device__ __align__(1024) __half g_a1x[(size_t)BATCH * D_IN];            // x    hi fp16
__device__ __align__(1024) __half g_a1f[(size_t)BATCH * NH];              // feat hi fp16
__device__ __align__(1024) __half g_b1[(size_t)(NH * KLR + NH) * NH];     // [v | mu] rows, hi fp16
__device__ __align__(1024) __half g_b1l[(size_t)NCLS * NH];               // Wl hi fp16
__device__ float g_rowsq[BATCH];
__device__ float g_msq[NH];
__device__ float g_c[NH * KLR];
__device__ float g_scale[NH];
__device__ float g_shift[NH];
__device__ double g_psum[NSEG * NH];
__device__ double g_psq[NSEG * NH];

// ================= HMMA fp16 GEMM (128x128 tile, 256 thr, 2 CTA/SM) =================
// C[m,n] = sum_d A1[m,d]*B1[n,d], A1 (M,Kd) hi fp16, B1 (Nrows,Kd) hi fp16.
// Output: col < Ncut  -> proj^2 4-group reduction: Pq[m*NqW + col/4] = sum_4 (C-c)^2
//         col >= Ncut -> Cs[m*Ns + (col-Ncut)] (+bias)
__global__ void __launch_bounds__(256)
gemm_mma(const __half* __restrict__ A1, const __half* __restrict__ B1,
         float* __restrict__ Pq, float* __restrict__ Cs, const float* __restrict__ cvec,
         int Mt, int Ncut, int Ntot, int Ns, int NqW, int Kd, const float* __restrict__ bias)
{
    extern __shared__ __align__(1024) char smem[];
    const uint32_t sbase = smem_u32(smem);
    const int tid = threadIdx.x;
    const int wid = tid >> 5;
    const int lane = tid & 31;
    const int wm = wid >> 2;          // 0..1  (m-warp, 64 rows)
    const int wn = wid & 3;           // 0..3  (n-warp, 32 cols)

    // banded raster: 8 n-tiles per band
    const int nt_total = (Ntot + 127) >> 7;
    const int bw0 = 8;
    const int per_band = Mt * bw0;
    const int band = blockIdx.x / per_band;
    const int rem = blockIdx.x % per_band;
    int nb = nt_total - band * bw0; if (nb > bw0) nb = bw0;
    const int mtile = rem / nb;
    const int ntile = band * bw0 + rem % nb;
    const int row0 = mtile * 128;
    const int col0 = ntile * 128;
    const int nk = Kd >> 6;

    float acc[4][4][4];
#pragma unroll
    for (int i = 0; i < 4; i++)
#pragma unroll
        for (int j = 0; j < 4; j++)
#pragma unroll
            for (int r = 0; r < 4; r++) acc[i][j][r] = 0.f;

    const int aRow = wm * 64 + (lane & 15);
    const int aK8 = (lane >> 4) * 8;
    const int bRow = wn * 32 + (lane & 7) + ((lane >> 4) & 1) * 8;
    const int bK8 = ((lane >> 3) & 1) * 8;

    auto issue = [&](int i) {
        if (i < nk) {
            const int s = i % STAGES;
            const uint32_t stA = sbase + s * STAGE_BYTES;
            const uint32_t stB = stA + 16384;
            const __half* Ab = A1 + (size_t)row0 * Kd + (i << 6);
            const __half* Bb = B1 + (i << 6);
#pragma unroll
            for (int it = 0; it < 4; it++) {
                int id = it * 256 + tid;
                int row = id >> 3, c = id & 7;
                uint32_t off = (uint32_t)(row * 128 + ((c * 16) ^ ((row & 7) << 4)));
                cp16(stA + off, Ab + (size_t)row * Kd + c * 8, 16);
            }
#pragma unroll
            for (int it = 0; it < 4; it++) {
                int id = it * 256 + tid;
                int row = id >> 3, c = id & 7;
                int gn = col0 + row;
                uint32_t bytes = (gn < Ntot) ? 16u : 0u;
                if (gn >= Ntot) gn = col0;
                uint32_t off = (uint32_t)(row * 128 + ((c * 16) ^ ((row & 7) << 4)));
                cp16(stB + off, Bb + (size_t)gn * Kd + c * 8, bytes);
            }
        }
        CP_COMMIT();
    };

#pragma unroll
    for (int i = 0; i < STAGES - 1; i++) issue(i);

    for (int i = 0; i < nk; i++) {
        CP_WAIT(STAGES - 2);
        __syncthreads();
        const int s = i % STAGES;
        const uint32_t stA = sbase + s * STAGE_BYTES;
        const uint32_t stB = stA + 16384;
#pragma unroll
        for (int ks = 0; ks < 4; ks++) {
            uint32_t a[4][4], b[2][4];
            const int kc = ks * 16;
#pragma unroll
            for (int mi = 0; mi < 4; mi++) {
                int row = aRow + mi * 16;
                uint32_t off = (uint32_t)(row * 128 + (((kc + aK8) * 2) ^ ((row & 7) << 4)));
                LDSM4(a[mi][0], a[mi][1], a[mi][2], a[mi][3], stA + off);
            }
#pragma unroll
            for (int nbk = 0; nbk < 2; nbk++) {
                int row = bRow + nbk * 16;
                uint32_t off = (uint32_t)(row * 128 + (((kc + bK8) * 2) ^ ((row & 7) << 4)));
                LDSM4(b[nbk][0], b[nbk][1], b[nbk][2], b[nbk][3], stB + off);
            }
#pragma unroll
            for (int mi = 0; mi < 4; mi++)
#pragma unroll
                for (int ni = 0; ni < 4; ni++)
                    MMA16816(acc[mi][ni], a[mi], b[ni >> 1][(ni & 1) * 2], b[ni >> 1][(ni & 1) * 2 + 1]);
        }
        issue(i + STAGES - 1);
    }

    // ---- epilogue: route P region (proj^2 reduce) vs S/plain region ----
#pragma unroll
    for (int mi = 0; mi < 4; mi++) {
        const int m = row0 + wm * 64 + mi * 16 + (lane >> 2);
#pragma unroll
        for (int ni = 0; ni < 4; ni++) {
            const int col = col0 + wn * 32 + ni * 8 + (lane & 3) * 2;
            float2 v0 = make_float2(acc[mi][ni][0], acc[mi][ni][1]);
            float2 v1 = make_float2(acc[mi][ni][2], acc[mi][ni][3]);
            if (col < Ncut) {
                float c0 = cvec[col], c1 = cvec[col + 1];
                float d00 = v0.x - c0, d01 = v0.y - c1;
                float d10 = v1.x - c0, d11 = v1.y - c1;
                float dd0 = d00 * d00 + d01 * d01;
                float dd1 = d10 * d10 + d11 * d11;
                float q0 = dd0 + __shfl_xor_sync(0xffffffffu, dd0, 1);
                float q1 = dd1 + __shfl_xor_sync(0xffffffffu, dd1, 1);
                if ((lane & 1) == 0) {
                    int g = col >> 2;
                    Pq[(size_t)m * NqW + g] = q0;
                    Pq[(size_t)(m + 8) * NqW + g] = q1;
                }
            } else {
                int sc = col - Ncut;
                if (sc < Ns) {
                    if (bias) {
                        float b0 = bias[sc], b1 = bias[sc + 1];
                        v0.x += b0; v0.y += b1; v1.x += b0; v1.y += b1;
                    }
                    *(float2*)(Cs + (size_t)m * Ns + sc) = v0;
                    *(float2*)(Cs + (size_t)(m + 8) * Ns + sc) = v1;
                }
            }
        }
    }
}

// ---------------- cast: fp32 -> fp16 ----------------
__global__ void castH(const float* __restrict__ src, __half* __restrict__ dst) {
    size_t i = (size_t)blockIdx.x * 256 + threadIdx.x;
    dst[i] = __float2half(src[i]);
}

// ---------------- row sum of squares (fp32 source) ----------------
__global__ void rowsq_kernel(const float* __restrict__ x, float* __restrict__ out, int D) {
    int b = blockIdx.x;
    const float* p = x + (size_t)b * D;
    float s = 0.f;
    for (int i = threadIdx.x; i < D; i += 256) { float v = p[i]; s = fmaf(v, v, s); }
    __shared__ float red[256];
    red[threadIdx.x] = s;
    __syncthreads();
    for (int off = 128; off > 0; off >>= 1) {
        if (threadIdx.x < off) red[threadIdx.x] += red[threadIdx.x + off];
        __syncthreads();
    }
    if (threadIdx.x == 0) out[b] = red[0];
}

// ---------------- row sum of squares (fp16 source) ----------------
__global__ void rowsq_half(const __half* __restrict__ f, float* __restrict__ out, int D) {
    int b = blockIdx.x;
    const __half* p = f + (size_t)b * D;
    float s = 0.f;
    for (int i = threadIdx.x; i < D; i += 256) {
        float v = __half2float(p[i]);
        s = fmaf(v, v, s);
    }
    __shared__ float red[256];
    red[threadIdx.x] = s;
    __syncthreads();
    for (int off = 128; off > 0; off >>= 1) {
        if (threadIdx.x < off) red[threadIdx.x] += red[threadIdx.x + off];
        __syncthreads();
    }
    if (threadIdx.x == 0) out[b] = red[0];
}

// ------- fused prep + cast: msq, c, and fp16 [v|mu] rows in one pass -------
__global__ void prep_cast(const float* __restrict__ mu, const float* __restrict__ v,
                          __half* __restrict__ B1,
                          float* __restrict__ msq, float* __restrict__ c, int D) {
    int n = blockIdx.x;
    const float* mp = mu + (size_t)n * D;
    const float* vp = v + (size_t)n * KLR * D;
    __half* bmu = B1 + ((size_t)(NH * KLR) + n) * D;
    __half* bv  = B1 + (size_t)n * KLR * D;
    float acc[5] = {0.f, 0.f, 0.f, 0.f, 0.f};
    for (int i = threadIdx.x; i < D; i += 256) {
        float m = mp[i];
        bmu[i] = __float2half(m);
        acc[0] = fmaf(m, m, acc[0]);
#pragma unroll
        for (int k = 0; k < KLR; k++) {
            float vv = vp[(size_t)k * D + i];
            bv[(size_t)k * D + i] = __float2half(vv);
            acc[k + 1] = fmaf(m, vv, acc[k + 1]);
        }
    }
    __shared__ float red[256];
    for (int j = 0; j < 5; j++) {
        red[threadIdx.x] = acc[j];
        __syncthreads();
        for (int off = 128; off > 0; off >>= 1) {
            if (threadIdx.x < off) red[threadIdx.x] += red[threadIdx.x + off];
            __syncthreads();
        }
        if (threadIdx.x == 0) {
            if (j == 0) msq[n] = red[0];
            else        c[n * KLR + (j - 1)] = red[0];
        }
        __syncthreads();
    }
}

// ------- fused quad epilogue + single-pass fp64 BN statistics -------
__global__ void quad_bnsum(const float* __restrict__ S, const float* __restrict__ Pq,
                           const float* __restrict__ rsq, const float* __restrict__ msq,
                           const float* __restrict__ lam,
                           float* __restrict__ t, double* __restrict__ psum,
                           double* __restrict__ psq, int mode) {
    int n = blockIdx.x * 256 + threadIdx.x;
    int seg = blockIdx.y;
    const int rows = BATCH / NSEG;
    float lamn = lam[n];
    float msqn = msq[n];
    double s = 0.0, s2 = 0.0;
    size_t b0 = (size_t)seg * rows;
    for (int r = 0; r < rows; r++) {
        size_t b = b0 + r;
        size_t idx = b * NH + n;
        float q = lamn * (rsq[b] - 2.f * S[idx] + msqn) + Pq[idx];
        float v = mode ? expf(-q * (1.0f / (float)NH)) : -q;
        t[idx] = v;
        double dv = (double)v;
        s += dv;
        s2 = fma(dv, dv, s2);
    }
    psum[seg * NH + n] = s;
    psq[seg * NH + n] = s2;
}

// ------- BN finalize: combine partials, var = E[x^2]-m^2 in fp64 -------
__global__ void bn_stats(const double* __restrict__ psum, const double* __restrict__ psq,
                         const float* __restrict__ g, const float* __restrict__ be,
                         float* __restrict__ scale, float* __restrict__ shift) {
    int n = blockIdx.x * 256 + threadIdx.x;
    double s = 0.0, s2 = 0.0;
    for (int i = 0; i < NSEG; i++) { s += psum[i * NH + n]; s2 += psq[i * NH + n]; }
    double mean = s * (1.0 / (double)BATCH);
    double var = s2 * (1.0 / (double)BATCH) - mean * mean;
    float rstd = (float)(1.0 / sqrt(var + (double)BN_EPS));
    float sc = g[n] * rstd;
    scale[n] = sc;
    shift[n] = be[n] - (float)mean * sc;
}

// applies BN (+optional relu), writes hi fp16 feat + optional fp32 outputs
__global__ void bn_apply(const float* __restrict__ t, const float* __restrict__ scale,
                         const float* __restrict__ shift,
                         __half* __restrict__ f1,
                         float* o1, float* o2, int relu) {
    size_t idx = (size_t)blockIdx.x * 256 + threadIdx.x;
    int n = (int)(idx & (NH - 1));
    float v = fmaf(t[idx], scale[n], shift[n]);
    if (relu) v = fmaxf(v, 0.f);
    f1[idx] = __float2half(v);
    if (o1) o1[idx] = v;
    if (o2) o2[idx] = v;
}

// ---------------- host orchestration ----------------
extern "C" void kernel_launch(void* const* d_in, const int* in_sizes, int n_in,
                              void* d_out, int out_size) {
    const float* x    = (const float*)d_in[0];
    const float* mu1  = (const float*)d_in[1];
    const float* lam1 = (const float*)d_in[2];
    const float* v1   = (const float*)d_in[3];
    const float* g1   = (const float*)d_in[4];
    const float* b1   = (const float*)d_in[5];
    const float* mu2  = (const float*)d_in[6];
    const float* lam2 = (const float*)d_in[7];
    const float* v2   = (const float*)d_in[8];
    const float* g2   = (const float*)d_in[9];
    const float* b2   = (const float*)d_in[10];
    const float* Wl   = (const float*)d_in[11];
    const float* bl   = (const float*)d_in[12];

    float *pS, *pPq, *pT, *pR, *pM, *pC, *pScale, *pShift;
    double *pPsum, *pPsq;
    __half *pA1x, *pA1f, *pB1, *pB1l;
    cudaGetSymbolAddress((void**)&pS, g_S);
    cudaGetSymbolAddress((void**)&pPq, g_Pq);
    cudaGetSymbolAddress((void**)&pT, g_t);
    cudaGetSymbolAddress((void**)&pA1x, g_a1x);
    cudaGetSymbolAddress((void**)&pA1f, g_a1f);
    cudaGetSymbolAddress((void**)&pB1, g_b1);
    cudaGetSymbolAddress((void**)&pB1l, g_b1l);
    cudaGetSymbolAddress((void**)&pR, g_rowsq);
    cudaGetSymbolAddress((void**)&pM, g_msq);
    cudaGetSymbolAddress((void**)&pC, g_c);
    cudaGetSymbolAddress((void**)&pScale, g_scale);
    cudaGetSymbolAddress((void**)&pShift, g_shift);
    cudaGetSymbolAddress((void**)&pPsum, g_psum);
    cudaGetSymbolAddress((void**)&pPsq, g_psq);

    cudaFuncSetAttribute(gemm_mma, cudaFuncAttributeMaxDynamicSharedMemorySize, SMEM_TOTAL);

    const size_t LOGITS_SZ = (size_t)BATCH * NCLS;
    const size_t FEAT_SZ   = (size_t)BATCH * NH;
    float* out = (float*)d_out;
    size_t extra = ((size_t)out_size > LOGITS_SZ) ? ((size_t)out_size - LOGITS_SZ) / FEAT_SZ : 0;
    float* f1dst = (extra >= 1) ? out + LOGITS_SZ : nullptr;
    float* f2a   = (extra >= 2) ? out + LOGITS_SZ + FEAT_SZ : nullptr;
    float* f2b   = (extra >= 3) ? out + LOGITS_SZ + 2 * FEAT_SZ : nullptr;

    dim3 bn_grid(NH / 256, NSEG);
    const int elem_blocks = (int)(((size_t)BATCH * NH) / 256);
    const int Mt = BATCH / 128;         // 64
    const int NMERGED = NH * (KLR + 1); // 10240
    const int merged_grid = Mt * (NMERGED / 128);  // 5120

    // ---------- Layer 1 ----------
    castH<<<(BATCH * D_IN) / 256, 256>>>(x, pA1x);
    prep_cast<<<NH, 256>>>(mu1, v1, pB1, pM, pC, D_IN);
    rowsq_kernel<<<BATCH, 256>>>(x, pR, D_IN);
    gemm_mma<<<merged_grid, 256, SMEM_TOTAL>>>(pA1x, pB1, pPq, pS, pC, Mt, NH * KLR, NMERGED, NH, NH, D_IN, nullptr);
    quad_bnsum<<<bn_grid, 256>>>(pS, pPq, pR, pM, lam1, pT, pPsum, pPsq, 0);
    bn_stats<<<NH / 256, 256>>>(pPsum, pPsq, g1, b1, pScale, pShift);
    bn_apply<<<elem_blocks, 256>>>(pT, pScale, pShift, pA1f, f1dst, nullptr, 0);

    // ---------- Layer 2 ----------
    prep_cast<<<NH, 256>>>(mu2, v2, pB1, pM, pC, NH);
    rowsq_half<<<BATCH, 256>>>(pA1f, pR, NH);
    gemm_mma<<<merged_grid, 256, SMEM_TOTAL>>>(pA1f, pB1, pPq, pS, pC, Mt, NH * KLR, NMERGED, NH, NH, NH, nullptr);
    quad_bnsum<<<bn_grid, 256>>>(pS, pPq, pR, pM, lam2, pT, pPsum, pPsq, 1);
    bn_stats<<<NH / 256, 256>>>(pPsum, pPsq, g2, b2, pScale, pShift);
    bn_apply<<<elem_blocks, 256>>>(pT, pScale, pShift, pA1f, f2a, f2b, 1);

    // ---------- Logits ----------
    castH<<<(NCLS * NH) / 256, 256>>>(Wl, pB1l);
    gemm_mma<<<Mt * ((NCLS + 127) / 128), 256, SMEM_TOTAL>>>(pA1f, pB1l, nullptr, out, nullptr, Mt, 0, NCLS, NCLS, 0, NH, bl);
}

// round 9
// speedup vs baseline: 1.8763x; 1.0510x over previous
#include <cuda_runtime.h>
#include <cuda_fp16.h>
#include <cstdint>

// Problem constants
#define BATCH 8192
#define D_IN  1024
#define NH    2048
#define KLR   4
#define NCLS  1000
#define BN_EPS 1e-5f
#define NSEG  32

#define STAGES 3
#define STAGE_BYTES 32768           // A 16KB (128x128B) | B 16KB (128x128B)
#define SMEM_TOTAL (STAGES * STAGE_BYTES)

static __device__ __forceinline__ uint32_t smem_u32(const void* p) {
    uint32_t a;
    asm("{ .reg .u64 t; cvta.to.shared.u64 t, %1; cvt.u32.u64 %0, t; }" : "=r"(a) : "l"(p));
    return a;
}
static __device__ __forceinline__ void cp16(uint32_t dst, const void* src, uint32_t bytes) {
    asm volatile("cp.async.cg.shared.global [%0], [%1], 16, %2;" :: "r"(dst), "l"(src), "r"(bytes) : "memory");
}
#define CP_COMMIT() asm volatile("cp.async.commit_group;" ::: "memory")
#define CP_WAIT(n)  asm volatile("cp.async.wait_group %0;" :: "n"(n) : "memory")
#define LDSM4(r0, r1, r2, r3, a) \
    asm volatile("ldmatrix.sync.aligned.m8n8.x4.shared.b16 {%0,%1,%2,%3}, [%4];" \
        : "=r"(r0), "=r"(r1), "=r"(r2), "=r"(r3) : "r"(a))
#define MMA16816(c, a, b0, b1) \
    asm volatile("mma.sync.aligned.m16n8k16.row.col.f32.f16.f16.f32 " \
        "{%0,%1,%2,%3},{%4,%5,%6,%7},{%8,%9},{%0,%1,%2,%3};" \
        : "+f"((c)[0]), "+f"((c)[1]), "+f"((c)[2]), "+f"((c)[3]) \
        : "r"((a)[0]), "r"((a)[1]), "r"((a)[2]), "r"((a)[3]), "r"(b0), "r"(b1))

// ---------------- static device scratch ----------------
__device__ float g_S[(size_t)BATCH * NH];
__device__ float g_Pq[(size_t)BATCH * NH];         // fused proj^2 sums
__device__ float g_t[(size_t)BATCH * NH];
__device__ __align__(1024) __half g_a1x[(size_t)BATCH * D_IN];            // x    hi fp16
__device__ __align__(1024) __half g_a1f[(size_t)BATCH * NH];              // feat hi fp16
__device__ __align__(1024) __half g_b1[(size_t)(NH * KLR + NH) * NH];     // [v | mu] rows, hi fp16
__device__ __align__(1024) __half g_b1l[(size_t)NCLS * NH];               // Wl hi fp16
__device__ float g_rowsq[BATCH];
__device__ float g_msq[NH];
__device__ float g_c[NH * KLR];
__device__ float g_scale[NH];
__device__ float g_shift[NH];
__device__ double g_psum[NSEG * NH];
__device__ double g_psq[NSEG * NH];

// ===== HMMA fp16 GEMM: 128x128 CTA, 4 warps (2x2), 64x64 warp tile, 2 CTA/SM =====
// C[m,n] = sum_d A1[m,d]*B1[n,d].
// Output: col < Ncut  -> proj^2 4-group reduce: Pq[m*NqW + col/4] = sum_4 (C-c)^2
//         col >= Ncut -> Cs[m*Ns + (col-Ncut)] (+bias)
__global__ void __launch_bounds__(128, 2)
gemm_mma(const __half* __restrict__ A1, const __half* __restrict__ B1,
         float* __restrict__ Pq, float* __restrict__ Cs, const float* __restrict__ cvec,
         int Mt, int Ncut, int Ntot, int Ns, int NqW, int Kd, const float* __restrict__ bias)
{
    extern __shared__ __align__(1024) char smem[];
    const uint32_t sbase = smem_u32(smem);
    const int tid = threadIdx.x;
    const int wid = tid >> 5;
    const int lane = tid & 31;
    const int wm = wid >> 1;          // 0..1 (m-warp, 64 rows)
    const int wn = wid & 1;           // 0..1 (n-warp, 64 cols)

    // banded raster: 8 n-tiles per band
    const int nt_total = (Ntot + 127) >> 7;
    const int bw0 = 8;
    const int per_band = Mt * bw0;
    const int band = blockIdx.x / per_band;
    const int rem = blockIdx.x % per_band;
    int nb = nt_total - band * bw0; if (nb > bw0) nb = bw0;
    const int mtile = rem / nb;
    const int ntile = band * bw0 + rem % nb;
    const int row0 = mtile * 128;
    const int col0 = ntile * 128;
    const int nk = Kd >> 6;

    float acc[4][8][4];
#pragma unroll
    for (int i = 0; i < 4; i++)
#pragma unroll
        for (int j = 0; j < 8; j++)
#pragma unroll
            for (int r = 0; r < 4; r++) acc[i][j][r] = 0.f;

    const int aRow = wm * 64 + (lane & 15);
    const int aK8 = (lane >> 4) * 8;
    const int bRow = wn * 64 + (lane & 7) + ((lane >> 4) & 1) * 8;
    const int bK8 = ((lane >> 3) & 1) * 8;

    auto issue = [&](int i) {
        if (i < nk) {
            const int s = i % STAGES;
            const uint32_t stA = sbase + s * STAGE_BYTES;
            const uint32_t stB = stA + 16384;
            const __half* Ab = A1 + (size_t)row0 * Kd + (i << 6);
            const __half* Bb = B1 + (i << 6);
#pragma unroll
            for (int it = 0; it < 8; it++) {
                int id = it * 128 + tid;
                int row = id >> 3, c = id & 7;
                uint32_t off = (uint32_t)(row * 128 + ((c * 16) ^ ((row & 7) << 4)));
                cp16(stA + off, Ab + (size_t)row * Kd + c * 8, 16);
            }
#pragma unroll
            for (int it = 0; it < 8; it++) {
                int id = it * 128 + tid;
                int row = id >> 3, c = id & 7;
                int gn = col0 + row;
                uint32_t bytes = (gn < Ntot) ? 16u : 0u;
                if (gn >= Ntot) gn = col0;
                uint32_t off = (uint32_t)(row * 128 + ((c * 16) ^ ((row & 7) << 4)));
                cp16(stB + off, Bb + (size_t)gn * Kd + c * 8, bytes);
            }
        }
        CP_COMMIT();
    };

#pragma unroll
    for (int i = 0; i < STAGES - 1; i++) issue(i);

    for (int i = 0; i < nk; i++) {
        CP_WAIT(STAGES - 2);
        __syncthreads();
        const int s = i % STAGES;
        const uint32_t stA = sbase + s * STAGE_BYTES;
        const uint32_t stB = stA + 16384;
#pragma unroll
        for (int ks = 0; ks < 4; ks++) {
            uint32_t a[4][4], b[4][4];
            const int kc = ks * 16;
#pragma unroll
            for (int mi = 0; mi < 4; mi++) {
                int row = aRow + mi * 16;
                uint32_t off = (uint32_t)(row * 128 + (((kc + aK8) * 2) ^ ((row & 7) << 4)));
                LDSM4(a[mi][0], a[mi][1], a[mi][2], a[mi][3], stA + off);
            }
#pragma unroll
            for (int nbk = 0; nbk < 4; nbk++) {
                int row = bRow + nbk * 16;
                uint32_t off = (uint32_t)(row * 128 + (((kc + bK8) * 2) ^ ((row & 7) << 4)));
                LDSM4(b[nbk][0], b[nbk][1], b[nbk][2], b[nbk][3], stB + off);
            }
#pragma unroll
            for (int mi = 0; mi < 4; mi++)
#pragma unroll
                for (int ni = 0; ni < 8; ni++)
                    MMA16816(acc[mi][ni], a[mi], b[ni >> 1][(ni & 1) * 2], b[ni >> 1][(ni & 1) * 2 + 1]);
        }
        issue(i + STAGES - 1);
    }

    // ---- epilogue: route P region (proj^2 reduce) vs S/plain region ----
#pragma unroll
    for (int mi = 0; mi < 4; mi++) {
        const int m = row0 + wm * 64 + mi * 16 + (lane >> 2);
#pragma unroll
        for (int ni = 0; ni < 8; ni++) {
            const int col = col0 + wn * 64 + ni * 8 + (lane & 3) * 2;
            float2 v0 = make_float2(acc[mi][ni][0], acc[mi][ni][1]);
            float2 v1 = make_float2(acc[mi][ni][2], acc[mi][ni][3]);
            if (col < Ncut) {
                float c0 = cvec[col], c1 = cvec[col + 1];
                float d00 = v0.x - c0, d01 = v0.y - c1;
                float d10 = v1.x - c0, d11 = v1.y - c1;
                float dd0 = d00 * d00 + d01 * d01;
                float dd1 = d10 * d10 + d11 * d11;
                float q0 = dd0 + __shfl_xor_sync(0xffffffffu, dd0, 1);
                float q1 = dd1 + __shfl_xor_sync(0xffffffffu, dd1, 1);
                if ((lane & 1) == 0) {
                    int g = col >> 2;
                    Pq[(size_t)m * NqW + g] = q0;
                    Pq[(size_t)(m + 8) * NqW + g] = q1;
                }
            } else {
                int sc = col - Ncut;
                if (sc < Ns) {
                    if (bias) {
                        float b0 = bias[sc], b1 = bias[sc + 1];
                        v0.x += b0; v0.y += b1; v1.x += b0; v1.y += b1;
                    }
                    *(float2*)(Cs + (size_t)m * Ns + sc) = v0;
                    *(float2*)(Cs + (size_t)(m + 8) * Ns + sc) = v1;
                }
            }
        }
    }
}

// ---------------- fused cast + row sum of squares (layer-1 input) ----------------
__global__ void castx_rowsq(const float* __restrict__ x, __half* __restrict__ xh,
                            float* __restrict__ rsq, int D) {
    int b = blockIdx.x;
    const float* p = x + (size_t)b * D;
    __half* o = xh + (size_t)b * D;
    float s = 0.f;
    for (int i = threadIdx.x; i < D; i += 256) {
        float v = p[i];
        o[i] = __float2half(v);
        s = fmaf(v, v, s);
    }
    __shared__ float red[256];
    red[threadIdx.x] = s;
    __syncthreads();
    for (int off = 128; off > 0; off >>= 1) {
        if (threadIdx.x < off) red[threadIdx.x] += red[threadIdx.x + off];
        __syncthreads();
    }
    if (threadIdx.x == 0) rsq[b] = red[0];
}

// ---------------- cast: fp32 -> fp16 ----------------
__global__ void castH(const float* __restrict__ src, __half* __restrict__ dst) {
    size_t i = (size_t)blockIdx.x * 256 + threadIdx.x;
    dst[i] = __float2half(src[i]);
}

// ------- fused prep + cast: msq, c, and fp16 [v|mu] rows in one pass -------
__global__ void prep_cast(const float* __restrict__ mu, const float* __restrict__ v,
                          __half* __restrict__ B1,
                          float* __restrict__ msq, float* __restrict__ c, int D) {
    int n = blockIdx.x;
    const float* mp = mu + (size_t)n * D;
    const float* vp = v + (size_t)n * KLR * D;
    __half* bmu = B1 + ((size_t)(NH * KLR) + n) * D;
    __half* bv  = B1 + (size_t)n * KLR * D;
    float acc[5] = {0.f, 0.f, 0.f, 0.f, 0.f};
    for (int i = threadIdx.x; i < D; i += 256) {
        float m = mp[i];
        bmu[i] = __float2half(m);
        acc[0] = fmaf(m, m, acc[0]);
#pragma unroll
        for (int k = 0; k < KLR; k++) {
            float vv = vp[(size_t)k * D + i];
            bv[(size_t)k * D + i] = __float2half(vv);
            acc[k + 1] = fmaf(m, vv, acc[k + 1]);
        }
    }
    __shared__ float red[256];
    for (int j = 0; j < 5; j++) {
        red[threadIdx.x] = acc[j];
        __syncthreads();
        for (int off = 128; off > 0; off >>= 1) {
            if (threadIdx.x < off) red[threadIdx.x] += red[threadIdx.x + off];
            __syncthreads();
        }
        if (threadIdx.x == 0) {
            if (j == 0) msq[n] = red[0];
            else        c[n * KLR + (j - 1)] = red[0];
        }
        __syncthreads();
    }
}

// ------- fused quad epilogue + single-pass fp64 BN statistics -------
__global__ void quad_bnsum(const float* __restrict__ S, const float* __restrict__ Pq,
                           const float* __restrict__ rsq, const float* __restrict__ msq,
                           const float* __restrict__ lam,
                           float* __restrict__ t, double* __restrict__ psum,
                           double* __restrict__ psq, int mode) {
    int n = blockIdx.x * 256 + threadIdx.x;
    int seg = blockIdx.y;
    const int rows = BATCH / NSEG;
    float lamn = lam[n];
    float msqn = msq[n];
    double s = 0.0, s2 = 0.0;
    size_t b0 = (size_t)seg * rows;
    for (int r = 0; r < rows; r++) {
        size_t b = b0 + r;
        size_t idx = b * NH + n;
        float q = lamn * (rsq[b] - 2.f * S[idx] + msqn) + Pq[idx];
        float v = mode ? expf(-q * (1.0f / (float)NH)) : -q;
        t[idx] = v;
        double dv = (double)v;
        s += dv;
        s2 = fma(dv, dv, s2);
    }
    psum[seg * NH + n] = s;
    psq[seg * NH + n] = s2;
}

// ------- BN finalize: combine partials, var = E[x^2]-m^2 in fp64 -------
__global__ void bn_stats(const double* __restrict__ psum, const double* __restrict__ psq,
                         const float* __restrict__ g, const float* __restrict__ be,
                         float* __restrict__ scale, float* __restrict__ shift) {
    int n = blockIdx.x * 256 + threadIdx.x;
    double s = 0.0, s2 = 0.0;
    for (int i = 0; i < NSEG; i++) { s += psum[i * NH + n]; s2 += psq[i * NH + n]; }
    double mean = s * (1.0 / (double)BATCH);
    double var = s2 * (1.0 / (double)BATCH) - mean * mean;
    float rstd = (float)(1.0 / sqrt(var + (double)BN_EPS));
    float sc = g[n] * rstd;
    scale[n] = sc;
    shift[n] = be[n] - (float)mean * sc;
}

// ------- BN apply (+optional relu) fused with next-layer rowsq -------
// one block per batch row; writes fp16 feat, optional fp32 copies, optional rowsq
__global__ void bn_apply(const float* __restrict__ t, const float* __restrict__ scale,
                         const float* __restrict__ shift,
                         __half* __restrict__ f1, float* __restrict__ rsq,
                         float* o1, float* o2, int relu) {
    int b = blockIdx.x;
    const float* tp = t + (size_t)b * NH;
    __half* fp = f1 + (size_t)b * NH;
    float s = 0.f;
    for (int n = threadIdx.x; n < NH; n += 256) {
        float v = fmaf(tp[n], scale[n], shift[n]);
        if (relu) v = fmaxf(v, 0.f);
        fp[n] = __float2half(v);
        s = fmaf(v, v, s);
        if (o1) o1[(size_t)b * NH + n] = v;
        if (o2) o2[(size_t)b * NH + n] = v;
    }
    if (rsq) {
        __shared__ float red[256];
        red[threadIdx.x] = s;
        __syncthreads();
        for (int off = 128; off > 0; off >>= 1) {
            if (threadIdx.x < off) red[threadIdx.x] += red[threadIdx.x + off];
            __syncthreads();
        }
        if (threadIdx.x == 0) rsq[b] = red[0];
    }
}

// ---------------- host orchestration ----------------
extern "C" void kernel_launch(void* const* d_in, const int* in_sizes, int n_in,
                              void* d_out, int out_size) {
    const float* x    = (const float*)d_in[0];
    const float* mu1  = (const float*)d_in[1];
    const float* lam1 = (const float*)d_in[2];
    const float* v1   = (const float*)d_in[3];
    const float* g1   = (const float*)d_in[4];
    const float* b1   = (const float*)d_in[5];
    const float* mu2  = (const float*)d_in[6];
    const float* lam2 = (const float*)d_in[7];
    const float* v2   = (const float*)d_in[8];
    const float* g2   = (const float*)d_in[9];
    const float* b2   = (const float*)d_in[10];
    const float* Wl   = (const float*)d_in[11];
    const float* bl   = (const float*)d_in[12];

    float *pS, *pPq, *pT, *pR, *pM, *pC, *pScale, *pShift;
    double *pPsum, *pPsq;
    __half *pA1x, *pA1f, *pB1, *pB1l;
    cudaGetSymbolAddress((void**)&pS, g_S);
    cudaGetSymbolAddress((void**)&pPq, g_Pq);
    cudaGetSymbolAddress((void**)&pT, g_t);
    cudaGetSymbolAddress((void**)&pA1x, g_a1x);
    cudaGetSymbolAddress((void**)&pA1f, g_a1f);
    cudaGetSymbolAddress((void**)&pB1, g_b1);
    cudaGetSymbolAddress((void**)&pB1l, g_b1l);
    cudaGetSymbolAddress((void**)&pR, g_rowsq);
    cudaGetSymbolAddress((void**)&pM, g_msq);
    cudaGetSymbolAddress((void**)&pC, g_c);
    cudaGetSymbolAddress((void**)&pScale, g_scale);
    cudaGetSymbolAddress((void**)&pShift, g_shift);
    cudaGetSymbolAddress((void**)&pPsum, g_psum);
    cudaGetSymbolAddress((void**)&pPsq, g_psq);

    cudaFuncSetAttribute(gemm_mma, cudaFuncAttributeMaxDynamicSharedMemorySize, SMEM_TOTAL);

    const size_t LOGITS_SZ = (size_t)BATCH * NCLS;
    const size_t FEAT_SZ   = (size_t)BATCH * NH;
    float* out = (float*)d_out;
    size_t extra = ((size_t)out_size > LOGITS_SZ) ? ((size_t)out_size - LOGITS_SZ) / FEAT_SZ : 0;
    float* f1dst = (extra >= 1) ? out + LOGITS_SZ : nullptr;
    float* f2a   = (extra >= 2) ? out + LOGITS_SZ + FEAT_SZ : nullptr;
    float* f2b   = (extra >= 3) ? out + LOGITS_SZ + 2 * FEAT_SZ : nullptr;

    dim3 bn_grid(NH / 256, NSEG);
    const int Mt = BATCH / 128;         // 64
    const int NMERGED = NH * (KLR + 1); // 10240
    const int merged_grid = Mt * (NMERGED / 128);  // 5120

    // ---------- Layer 1 ----------
    castx_rowsq<<<BATCH, 256>>>(x, pA1x, pR, D_IN);
    prep_cast<<<NH, 256>>>(mu1, v1, pB1, pM, pC, D_IN);
    gemm_mma<<<merged_grid, 128, SMEM_TOTAL>>>(pA1x, pB1, pPq, pS, pC, Mt, NH * KLR, NMERGED, NH, NH, D_IN, nullptr);
    quad_bnsum<<<bn_grid, 256>>>(pS, pPq, pR, pM, lam1, pT, pPsum, pPsq, 0);
    bn_stats<<<NH / 256, 256>>>(pPsum, pPsq, g1, b1, pScale, pShift);
    bn_apply<<<BATCH, 256>>>(pT, pScale, pShift, pA1f, pR, f1dst, nullptr, 0);

    // ---------- Layer 2 ----------
    prep_cast<<<NH, 256>>>(mu2, v2, pB1, pM, pC, NH);
    gemm_mma<<<merged_grid, 128, SMEM_TOTAL>>>(pA1f, pB1, pPq, pS, pC, Mt, NH * KLR, NMERGED, NH, NH, NH, nullptr);
    quad_bnsum<<<bn_grid, 256>>>(pS, pPq, pR, pM, lam2, pT, pPsum, pPsq, 1);
    bn_stats<<<NH / 256, 256>>>(pPsum, pPsq, g2, b2, pScale, pShift);
    bn_apply<<<BATCH, 256>>>(pT, pScale, pShift, pA1f, nullptr, f2a, f2b, 1);

    // ---------- Logits ----------
    castH<<<(NCLS * NH) / 256, 256>>>(Wl, pB1l);
    gemm_mma<<<Mt * ((NCLS + 127) / 128), 128, SMEM_TOTAL>>>(pA1f, pB1l, nullptr, out, nullptr, Mt, 0, NCLS, NCLS, 0, NH, bl);
}

// round 10
// speedup vs baseline: 1.9176x; 1.0220x over previous
#include <cuda_runtime.h>
#include <cuda_fp16.h>
#include <cstdint>

// Problem constants
#define BATCH 8192
#define D_IN  1024
#define NH    2048
#define KLR   4
#define NCLS  1000
#define BN_EPS 1e-5f
#define NSEG  128

#define STAGES 3
#define STAGE_BYTES 32768           // A 16KB (128x128B) | B 16KB (128x128B)
#define SMEM_TOTAL (STAGES * STAGE_BYTES)

static __device__ __forceinline__ uint32_t smem_u32(const void* p) {
    uint32_t a;
    asm("{ .reg .u64 t; cvta.to.shared.u64 t, %1; cvt.u32.u64 %0, t; }" : "=r"(a) : "l"(p));
    return a;
}
static __device__ __forceinline__ void cp16(uint32_t dst, const void* src, uint32_t bytes) {
    asm volatile("cp.async.cg.shared.global [%0], [%1], 16, %2;" :: "r"(dst), "l"(src), "r"(bytes) : "memory");
}
#define CP_COMMIT() asm volatile("cp.async.commit_group;" ::: "memory")
#define CP_WAIT(n)  asm volatile("cp.async.wait_group %0;" :: "n"(n) : "memory")
#define LDSM4(r0, r1, r2, r3, a) \
    asm volatile("ldmatrix.sync.aligned.m8n8.x4.shared.b16 {%0,%1,%2,%3}, [%4];" \
        : "=r"(r0), "=r"(r1), "=r"(r2), "=r"(r3) : "r"(a))
#define MMA16816(c, a, b0, b1) \
    asm volatile("mma.sync.aligned.m16n8k16.row.col.f32.f16.f16.f32 " \
        "{%0,%1,%2,%3},{%4,%5,%6,%7},{%8,%9},{%0,%1,%2,%3};" \
        : "+f"((c)[0]), "+f"((c)[1]), "+f"((c)[2]), "+f"((c)[3]) \
        : "r"((a)[0]), "r"((a)[1]), "r"((a)[2]), "r"((a)[3]), "r"(b0), "r"(b1))

// ---------------- static device scratch ----------------
__device__ float g_S[(size_t)BATCH * NH];
__device__ float g_Pq[(size_t)BATCH * NH];
__device__ float g_t[(size_t)BATCH * NH];
__device__ __align__(1024) __half g_a1x[(size_t)BATCH * D_IN];
__device__ __align__(1024) __half g_a1f[(size_t)BATCH * NH];
__device__ __align__(1024) __half g_b1[(size_t)(NH * KLR + NH) * NH];
__device__ __align__(1024) __half g_b1l[(size_t)NCLS * NH];
__device__ float g_rowsq[BATCH];
__device__ float g_msq[NH];
__device__ float g_c[NH * KLR];
__device__ float g_scale[NH];
__device__ float g_shift[NH];
__device__ double g_psum[NSEG * NH];
__device__ double g_psq[NSEG * NH];

// ===== HMMA fp16 GEMM: 128x128 CTA, 4 warps (2x2), 64x64 warp tile, 2 CTA/SM =====
// Software-pipelined LDSM double buffering across ks steps.
__global__ void __launch_bounds__(128, 2)
gemm_mma(const __half* __restrict__ A1, const __half* __restrict__ B1,
         float* __restrict__ Pq, float* __restrict__ Cs, const float* __restrict__ cvec,
         int Mt, int Ncut, int Ntot, int Ns, int NqW, int Kd, const float* __restrict__ bias)
{
    extern __shared__ __align__(1024) char smem[];
    const uint32_t sbase = smem_u32(smem);
    const int tid = threadIdx.x;
    const int wid = tid >> 5;
    const int lane = tid & 31;
    const int wm = wid >> 1;
    const int wn = wid & 1;

    const int nt_total = (Ntot + 127) >> 7;
    const int bw0 = 8;
    const int per_band = Mt * bw0;
    const int band = blockIdx.x / per_band;
    const int rem = blockIdx.x % per_band;
    int nb = nt_total - band * bw0; if (nb > bw0) nb = bw0;
    const int mtile = rem / nb;
    const int ntile = band * bw0 + rem % nb;
    const int row0 = mtile * 128;
    const int col0 = ntile * 128;
    const int nk = Kd >> 6;

    float acc[4][8][4];
#pragma unroll
    for (int i = 0; i < 4; i++)
#pragma unroll
        for (int j = 0; j < 8; j++)
#pragma unroll
            for (int r = 0; r < 4; r++) acc[i][j][r] = 0.f;

    const int aRow = wm * 64 + (lane & 15);
    const int aK8 = (lane >> 4) * 8;
    const int bRow = wn * 64 + (lane & 7) + ((lane >> 4) & 1) * 8;
    const int bK8 = ((lane >> 3) & 1) * 8;

    auto issue = [&](int i) {
        if (i < nk) {
            const int s = i % STAGES;
            const uint32_t stA = sbase + s * STAGE_BYTES;
            const uint32_t stB = stA + 16384;
            const __half* Ab = A1 + (size_t)row0 * Kd + (i << 6);
            const __half* Bb = B1 + (i << 6);
#pragma unroll
            for (int it = 0; it < 8; it++) {
                int id = it * 128 + tid;
                int row = id >> 3, c = id & 7;
                uint32_t off = (uint32_t)(row * 128 + ((c * 16) ^ ((row & 7) << 4)));
                cp16(stA + off, Ab + (size_t)row * Kd + c * 8, 16);
            }
#pragma unroll
            for (int it = 0; it < 8; it++) {
                int id = it * 128 + tid;
                int row = id >> 3, c = id & 7;
                int gn = col0 + row;
                uint32_t bytes = (gn < Ntot) ? 16u : 0u;
                if (gn >= Ntot) gn = col0;
                uint32_t off = (uint32_t)(row * 128 + ((c * 16) ^ ((row & 7) << 4)));
                cp16(stB + off, Bb + (size_t)gn * Kd + c * 8, bytes);
            }
        }
        CP_COMMIT();
    };

#pragma unroll
    for (int i = 0; i < STAGES - 1; i++) issue(i);

    for (int i = 0; i < nk; i++) {
        CP_WAIT(STAGES - 2);
        __syncthreads();
        const int s = i % STAGES;
        const uint32_t stA = sbase + s * STAGE_BYTES;
        const uint32_t stB = stA + 16384;

        uint32_t a[2][4][4], b[2][4][4];
        // prologue: load fragments for ks=0 into buffer 0
#pragma unroll
        for (int mi = 0; mi < 4; mi++) {
            int row = aRow + mi * 16;
            uint32_t off = (uint32_t)(row * 128 + ((aK8 * 2) ^ ((row & 7) << 4)));
            LDSM4(a[0][mi][0], a[0][mi][1], a[0][mi][2], a[0][mi][3], stA + off);
        }
#pragma unroll
        for (int nbk = 0; nbk < 4; nbk++) {
            int row = bRow + nbk * 16;
            uint32_t off = (uint32_t)(row * 128 + ((bK8 * 2) ^ ((row & 7) << 4)));
            LDSM4(b[0][nbk][0], b[0][nbk][1], b[0][nbk][2], b[0][nbk][3], stB + off);
        }

#pragma unroll
        for (int ks = 0; ks < 4; ks++) {
            const int cur = ks & 1;
            const int nxt = cur ^ 1;
            if (ks < 3) {
                const int kc = (ks + 1) * 16;
#pragma unroll
                for (int mi = 0; mi < 4; mi++) {
                    int row = aRow + mi * 16;
                    uint32_t off = (uint32_t)(row * 128 + (((kc + aK8) * 2) ^ ((row & 7) << 4)));
                    LDSM4(a[nxt][mi][0], a[nxt][mi][1], a[nxt][mi][2], a[nxt][mi][3], stA + off);
                }
#pragma unroll
                for (int nbk = 0; nbk < 4; nbk++) {
                    int row = bRow + nbk * 16;
                    uint32_t off = (uint32_t)(row * 128 + (((kc + bK8) * 2) ^ ((row & 7) << 4)));
                    LDSM4(b[nxt][nbk][0], b[nxt][nbk][1], b[nxt][nbk][2], b[nxt][nbk][3], stB + off);
                }
            }
#pragma unroll
            for (int mi = 0; mi < 4; mi++)
#pragma unroll
                for (int ni = 0; ni < 8; ni++)
                    MMA16816(acc[mi][ni], a[cur][mi],
                             b[cur][ni >> 1][(ni & 1) * 2], b[cur][ni >> 1][(ni & 1) * 2 + 1]);
        }
        issue(i + STAGES - 1);
    }

    // ---- epilogue ----
#pragma unroll
    for (int mi = 0; mi < 4; mi++) {
        const int m = row0 + wm * 64 + mi * 16 + (lane >> 2);
#pragma unroll
        for (int ni = 0; ni < 8; ni++) {
            const int col = col0 + wn * 64 + ni * 8 + (lane & 3) * 2;
            float2 v0 = make_float2(acc[mi][ni][0], acc[mi][ni][1]);
            float2 v1 = make_float2(acc[mi][ni][2], acc[mi][ni][3]);
            if (col < Ncut) {
                float c0 = cvec[col], c1 = cvec[col + 1];
                float d00 = v0.x - c0, d01 = v0.y - c1;
                float d10 = v1.x - c0, d11 = v1.y - c1;
                float dd0 = d00 * d00 + d01 * d01;
                float dd1 = d10 * d10 + d11 * d11;
                float q0 = dd0 + __shfl_xor_sync(0xffffffffu, dd0, 1);
                float q1 = dd1 + __shfl_xor_sync(0xffffffffu, dd1, 1);
                if ((lane & 1) == 0) {
                    int g = col >> 2;
                    Pq[(size_t)m * NqW + g] = q0;
                    Pq[(size_t)(m + 8) * NqW + g] = q1;
                }
            } else {
                int sc = col - Ncut;
                if (sc < Ns) {
                    if (bias) {
                        float b0 = bias[sc], b1 = bias[sc + 1];
                        v0.x += b0; v0.y += b1; v1.x += b0; v1.y += b1;
                    }
                    *(float2*)(Cs + (size_t)m * Ns + sc) = v0;
                    *(float2*)(Cs + (size_t)(m + 8) * Ns + sc) = v1;
                }
            }
        }
    }
}

// ---------------- fused cast + row sum of squares (layer-1 input) ----------------
__global__ void castx_rowsq(const float* __restrict__ x, __half* __restrict__ xh,
                            float* __restrict__ rsq, int D) {
    int b = blockIdx.x;
    const float* p = x + (size_t)b * D;
    __half* o = xh + (size_t)b * D;
    float s = 0.f;
    for (int i = threadIdx.x; i < D; i += 256) {
        float v = p[i];
        o[i] = __float2half(v);
        s = fmaf(v, v, s);
    }
    __shared__ float red[256];
    red[threadIdx.x] = s;
    __syncthreads();
    for (int off = 128; off > 0; off >>= 1) {
        if (threadIdx.x < off) red[threadIdx.x] += red[threadIdx.x + off];
        __syncthreads();
    }
    if (threadIdx.x == 0) rsq[b] = red[0];
}

// ---------------- cast: fp32 -> fp16 ----------------
__global__ void castH(const float* __restrict__ src, __half* __restrict__ dst) {
    size_t i = (size_t)blockIdx.x * 256 + threadIdx.x;
    dst[i] = __float2half(src[i]);
}

// ------- fused prep + cast -------
__global__ void prep_cast(const float* __restrict__ mu, const float* __restrict__ v,
                          __half* __restrict__ B1,
                          float* __restrict__ msq, float* __restrict__ c, int D) {
    int n = blockIdx.x;
    const float* mp = mu + (size_t)n * D;
    const float* vp = v + (size_t)n * KLR * D;
    __half* bmu = B1 + ((size_t)(NH * KLR) + n) * D;
    __half* bv  = B1 + (size_t)n * KLR * D;
    float acc[5] = {0.f, 0.f, 0.f, 0.f, 0.f};
    for (int i = threadIdx.x; i < D; i += 256) {
        float m = mp[i];
        bmu[i] = __float2half(m);
        acc[0] = fmaf(m, m, acc[0]);
#pragma unroll
        for (int k = 0; k < KLR; k++) {
            float vv = vp[(size_t)k * D + i];
            bv[(size_t)k * D + i] = __float2half(vv);
            acc[k + 1] = fmaf(m, vv, acc[k + 1]);
        }
    }
    __shared__ float red[256];
    for (int j = 0; j < 5; j++) {
        red[threadIdx.x] = acc[j];
        __syncthreads();
        for (int off = 128; off > 0; off >>= 1) {
            if (threadIdx.x < off) red[threadIdx.x] += red[threadIdx.x + off];
            __syncthreads();
        }
        if (threadIdx.x == 0) {
            if (j == 0) msq[n] = red[0];
            else        c[n * KLR + (j - 1)] = red[0];
        }
        __syncthreads();
    }
}

// ------- fused quad epilogue + single-pass fp64 BN statistics -------
__global__ void quad_bnsum(const float* __restrict__ S, const float* __restrict__ Pq,
                           const float* __restrict__ rsq, const float* __restrict__ msq,
                           const float* __restrict__ lam,
                           float* __restrict__ t, double* __restrict__ psum,
                           double* __restrict__ psq, int mode) {
    int n = blockIdx.x * 256 + threadIdx.x;
    int seg = blockIdx.y;
    const int rows = BATCH / NSEG;
    float lamn = lam[n];
    float msqn = msq[n];
    double s = 0.0, s2 = 0.0;
    size_t b0 = (size_t)seg * rows;
    for (int r = 0; r < rows; r++) {
        size_t b = b0 + r;
        size_t idx = b * NH + n;
        float q = lamn * (rsq[b] - 2.f * S[idx] + msqn) + Pq[idx];
        float v = mode ? expf(-q * (1.0f / (float)NH)) : -q;
        t[idx] = v;
        double dv = (double)v;
        s += dv;
        s2 = fma(dv, dv, s2);
    }
    psum[seg * NH + n] = s;
    psq[seg * NH + n] = s2;
}

// ------- BN finalize -------
__global__ void bn_stats(const double* __restrict__ psum, const double* __restrict__ psq,
                         const float* __restrict__ g, const float* __restrict__ be,
                         float* __restrict__ scale, float* __restrict__ shift) {
    int n = blockIdx.x * 256 + threadIdx.x;
    double s = 0.0, s2 = 0.0;
    for (int i = 0; i < NSEG; i++) { s += psum[i * NH + n]; s2 += psq[i * NH + n]; }
    double mean = s * (1.0 / (double)BATCH);
    double var = s2 * (1.0 / (double)BATCH) - mean * mean;
    float rstd = (float)(1.0 / sqrt(var + (double)BN_EPS));
    float sc = g[n] * rstd;
    scale[n] = sc;
    shift[n] = be[n] - (float)mean * sc;
}

// ------- BN apply fused with next-layer rowsq -------
__global__ void bn_apply(const float* __restrict__ t, const float* __restrict__ scale,
                         const float* __restrict__ shift,
                         __half* __restrict__ f1, float* __restrict__ rsq,
                         float* o1, float* o2, int relu) {
    int b = blockIdx.x;
    const float* tp = t + (size_t)b * NH;
    __half* fp = f1 + (size_t)b * NH;
    float s = 0.f;
    for (int n = threadIdx.x; n < NH; n += 256) {
        float v = fmaf(tp[n], scale[n], shift[n]);
        if (relu) v = fmaxf(v, 0.f);
        fp[n] = __float2half(v);
        s = fmaf(v, v, s);
        if (o1) o1[(size_t)b * NH + n] = v;
        if (o2) o2[(size_t)b * NH + n] = v;
    }
    if (rsq) {
        __shared__ float red[256];
        red[threadIdx.x] = s;
        __syncthreads();
        for (int off = 128; off > 0; off >>= 1) {
            if (threadIdx.x < off) red[threadIdx.x] += red[threadIdx.x + off];
            __syncthreads();
        }
        if (threadIdx.x == 0) rsq[b] = red[0];
    }
}

// ---------------- host orchestration ----------------
extern "C" void kernel_launch(void* const* d_in, const int* in_sizes, int n_in,
                              void* d_out, int out_size) {
    const float* x    = (const float*)d_in[0];
    const float* mu1  = (const float*)d_in[1];
    const float* lam1 = (const float*)d_in[2];
    const float* v1   = (const float*)d_in[3];
    const float* g1   = (const float*)d_in[4];
    const float* b1   = (const float*)d_in[5];
    const float* mu2  = (const float*)d_in[6];
    const float* lam2 = (const float*)d_in[7];
    const float* v2   = (const float*)d_in[8];
    const float* g2   = (const float*)d_in[9];
    const float* b2   = (const float*)d_in[10];
    const float* Wl   = (const float*)d_in[11];
    const float* bl   = (const float*)d_in[12];

    float *pS, *pPq, *pT, *pR, *pM, *pC, *pScale, *pShift;
    double *pPsum, *pPsq;
    __half *pA1x, *pA1f, *pB1, *pB1l;
    cudaGetSymbolAddress((void**)&pS, g_S);
    cudaGetSymbolAddress((void**)&pPq, g_Pq);
    cudaGetSymbolAddress((void**)&pT, g_t);
    cudaGetSymbolAddress((void**)&pA1x, g_a1x);
    cudaGetSymbolAddress((void**)&pA1f, g_a1f);
    cudaGetSymbolAddress((void**)&pB1, g_b1);
    cudaGetSymbolAddress((void**)&pB1l, g_b1l);
    cudaGetSymbolAddress((void**)&pR, g_rowsq);
    cudaGetSymbolAddress((void**)&pM, g_msq);
    cudaGetSymbolAddress((void**)&pC, g_c);
    cudaGetSymbolAddress((void**)&pScale, g_scale);
    cudaGetSymbolAddress((void**)&pShift, g_shift);
    cudaGetSymbolAddress((void**)&pPsum, g_psum);
    cudaGetSymbolAddress((void**)&pPsq, g_psq);

    cudaFuncSetAttribute(gemm_mma, cudaFuncAttributeMaxDynamicSharedMemorySize, SMEM_TOTAL);

    const size_t LOGITS_SZ = (size_t)BATCH * NCLS;
    const size_t FEAT_SZ   = (size_t)BATCH * NH;
    float* out = (float*)d_out;
    size_t extra = ((size_t)out_size > LOGITS_SZ) ? ((size_t)out_size - LOGITS_SZ) / FEAT_SZ : 0;
    float* f1dst = (extra >= 1) ? out + LOGITS_SZ : nullptr;
    float* f2a   = (extra >= 2) ? out + LOGITS_SZ + FEAT_SZ : nullptr;
    float* f2b   = (extra >= 3) ? out + LOGITS_SZ + 2 * FEAT_SZ : nullptr;

    dim3 bn_grid(NH / 256, NSEG);
    const int Mt = BATCH / 128;
    const int NMERGED = NH * (KLR + 1);
    const int merged_grid = Mt * (NMERGED / 128);

    // ---------- Layer 1 ----------
    castx_rowsq<<<BATCH, 256>>>(x, pA1x, pR, D_IN);
    prep_cast<<<NH, 256>>>(mu1, v1, pB1, pM, pC, D_IN);
    gemm_mma<<<merged_grid, 128, SMEM_TOTAL>>>(pA1x, pB1, pPq, pS, pC, Mt, NH * KLR, NMERGED, NH, NH, D_IN, nullptr);
    quad_bnsum<<<bn_grid, 256>>>(pS, pPq, pR, pM, lam1, pT, pPsum, pPsq, 0);
    bn_stats<<<NH / 256, 256>>>(pPsum, pPsq, g1, b1, pScale, pShift);
    bn_apply<<<BATCH, 256>>>(pT, pScale, pShift, pA1f, pR, f1dst, nullptr, 0);

    // ---------- Layer 2 ----------
    prep_cast<<<NH, 256>>>(mu2, v2, pB1, pM, pC, NH);
    gemm_mma<<<merged_grid, 128, SMEM_TOTAL>>>(pA1f, pB1, pPq, pS, pC, Mt, NH * KLR, NMERGED, NH, NH, NH, nullptr);
    quad_bnsum<<<bn_grid, 256>>>(pS, pPq, pR, pM, lam2, pT, pPsum, pPsq, 1);
    bn_stats<<<NH / 256, 256>>>(pPsum, pPsq, g2, b2, pScale, pShift);
    bn_apply<<<BATCH, 256>>>(pT, pScale, pShift, pA1f, nullptr, f2a, f2b, 1);

    // ---------- Logits ----------
    castH<<<(NCLS * NH) / 256, 256>>>(Wl, pB1l);
    gemm_mma<<<Mt * ((NCLS + 127) / 128), 128, SMEM_TOTAL>>>(pA1f, pB1l, nullptr, out, nullptr, Mt, 0, NCLS, NCLS, 0, NH, bl);
}

// round 11
// speedup vs baseline: 2.0069x; 1.0465x over previous
#include <cuda_runtime.h>
#include <cuda_fp16.h>
#include <cstdint>

// Problem constants
#define BATCH 8192
#define D_IN  1024
#define NH    2048
#define KLR   4
#define NCLS  1000
#define BN_EPS 1e-5f
#define NSEG  128

#define STAGES 3
#define STAGE_BYTES 32768           // A 16KB (128x128B) | B 16KB (128x128B)
#define SMEM_TOTAL (STAGES * STAGE_BYTES)

static __device__ __forceinline__ uint32_t smem_u32(const void* p) {
    uint32_t a;
    asm("{ .reg .u64 t; cvta.to.shared.u64 t, %1; cvt.u32.u64 %0, t; }" : "=r"(a) : "l"(p));
    return a;
}
static __device__ __forceinline__ void cp16(uint32_t dst, const void* src, uint32_t bytes) {
    asm volatile("cp.async.cg.shared.global [%0], [%1], 16, %2;" :: "r"(dst), "l"(src), "r"(bytes) : "memory");
}
#define CP_COMMIT() asm volatile("cp.async.commit_group;" ::: "memory")
#define CP_WAIT(n)  asm volatile("cp.async.wait_group %0;" :: "n"(n) : "memory")
#define LDSM4(r0, r1, r2, r3, a) \
    asm volatile("ldmatrix.sync.aligned.m8n8.x4.shared.b16 {%0,%1,%2,%3}, [%4];" \
        : "=r"(r0), "=r"(r1), "=r"(r2), "=r"(r3) : "r"(a))
#define MMA16816(c, a, b0, b1) \
    asm volatile("mma.sync.aligned.m16n8k16.row.col.f32.f16.f16.f32 " \
        "{%0,%1,%2,%3},{%4,%5,%6,%7},{%8,%9},{%0,%1,%2,%3};" \
        : "+f"((c)[0]), "+f"((c)[1]), "+f"((c)[2]), "+f"((c)[3]) \
        : "r"((a)[0]), "r"((a)[1]), "r"((a)[2]), "r"((a)[3]), "r"(b0), "r"(b1))

// ---------------- static device scratch ----------------
__device__ float g_S[(size_t)BATCH * NH];
__device__ float g_Pq[(size_t)BATCH * NH];
__device__ float g_t[(size_t)BATCH * NH];
__device__ __align__(1024) __half g_a1x[(size_t)BATCH * D_IN];
__device__ __align__(1024) __half g_a1f[(size_t)BATCH * NH];
__device__ __align__(1024) __half g_b1[(size_t)(NH * KLR + NH) * NH];
__device__ __align__(1024) __half g_b1l[(size_t)NCLS * NH];
__device__ float g_rowsq[BATCH];
__device__ float g_msq[NH];
__device__ float g_c[NH * KLR];
__device__ float g_scale[NH];
__device__ float g_shift[NH];
__device__ float g_psum[NSEG * NH];
__device__ float g_psq[NSEG * NH];

// ===== HMMA fp16 GEMM: 128x128 CTA, 4 warps (2x2), 64x64 warp tile, 2 CTA/SM =====
__global__ void __launch_bounds__(128, 2)
gemm_mma(const __half* __restrict__ A1, const __half* __restrict__ B1,
         float* __restrict__ Pq, float* __restrict__ Cs, const float* __restrict__ cvec,
         int Mt, int Ncut, int Ntot, int Ns, int NqW, int Kd, const float* __restrict__ bias)
{
    extern __shared__ __align__(1024) char smem[];
    const uint32_t sbase = smem_u32(smem);
    const int tid = threadIdx.x;
    const int wid = tid >> 5;
    const int lane = tid & 31;
    const int wm = wid >> 1;
    const int wn = wid & 1;

    const int nt_total = (Ntot + 127) >> 7;
    const int bw0 = 8;
    const int per_band = Mt * bw0;
    const int band = blockIdx.x / per_band;
    const int rem = blockIdx.x % per_band;
    int nb = nt_total - band * bw0; if (nb > bw0) nb = bw0;
    const int mtile = rem / nb;
    const int ntile = band * bw0 + rem % nb;
    const int row0 = mtile * 128;
    const int col0 = ntile * 128;
    const int nk = Kd >> 6;

    float acc[4][8][4];
#pragma unroll
    for (int i = 0; i < 4; i++)
#pragma unroll
        for (int j = 0; j < 8; j++)
#pragma unroll
            for (int r = 0; r < 4; r++) acc[i][j][r] = 0.f;

    const int aRow = wm * 64 + (lane & 15);
    const int aK8 = (lane >> 4) * 8;
    const int bRow = wn * 64 + (lane & 7) + ((lane >> 4) & 1) * 8;
    const int bK8 = ((lane >> 3) & 1) * 8;

    auto issue = [&](int i) {
        if (i < nk) {
            const int s = i % STAGES;
            const uint32_t stA = sbase + s * STAGE_BYTES;
            const uint32_t stB = stA + 16384;
            const __half* Ab = A1 + (size_t)row0 * Kd + (i << 6);
            const __half* Bb = B1 + (i << 6);
#pragma unroll
            for (int it = 0; it < 8; it++) {
                int id = it * 128 + tid;
                int row = id >> 3, c = id & 7;
                uint32_t off = (uint32_t)(row * 128 + ((c * 16) ^ ((row & 7) << 4)));
                cp16(stA + off, Ab + (size_t)row * Kd + c * 8, 16);
            }
#pragma unroll
            for (int it = 0; it < 8; it++) {
                int id = it * 128 + tid;
                int row = id >> 3, c = id & 7;
                int gn = col0 + row;
                uint32_t bytes = (gn < Ntot) ? 16u : 0u;
                if (gn >= Ntot) gn = col0;
                uint32_t off = (uint32_t)(row * 128 + ((c * 16) ^ ((row & 7) << 4)));
                cp16(stB + off, Bb + (size_t)gn * Kd + c * 8, bytes);
            }
        }
        CP_COMMIT();
    };

#pragma unroll
    for (int i = 0; i < STAGES - 1; i++) issue(i);

    for (int i = 0; i < nk; i++) {
        CP_WAIT(STAGES - 2);
        __syncthreads();
        const int s = i % STAGES;
        const uint32_t stA = sbase + s * STAGE_BYTES;
        const uint32_t stB = stA + 16384;

        uint32_t a[2][4][4], b[2][4][4];
#pragma unroll
        for (int mi = 0; mi < 4; mi++) {
            int row = aRow + mi * 16;
            uint32_t off = (uint32_t)(row * 128 + ((aK8 * 2) ^ ((row & 7) << 4)));
            LDSM4(a[0][mi][0], a[0][mi][1], a[0][mi][2], a[0][mi][3], stA + off);
        }
#pragma unroll
        for (int nbk = 0; nbk < 4; nbk++) {
            int row = bRow + nbk * 16;
            uint32_t off = (uint32_t)(row * 128 + ((bK8 * 2) ^ ((row & 7) << 4)));
            LDSM4(b[0][nbk][0], b[0][nbk][1], b[0][nbk][2], b[0][nbk][3], stB + off);
        }

#pragma unroll
        for (int ks = 0; ks < 4; ks++) {
            const int cur = ks & 1;
            const int nxt = cur ^ 1;
            if (ks < 3) {
                const int kc = (ks + 1) * 16;
#pragma unroll
                for (int mi = 0; mi < 4; mi++) {
                    int row = aRow + mi * 16;
                    uint32_t off = (uint32_t)(row * 128 + (((kc + aK8) * 2) ^ ((row & 7) << 4)));
                    LDSM4(a[nxt][mi][0], a[nxt][mi][1], a[nxt][mi][2], a[nxt][mi][3], stA + off);
                }
#pragma unroll
                for (int nbk = 0; nbk < 4; nbk++) {
                    int row = bRow + nbk * 16;
                    uint32_t off = (uint32_t)(row * 128 + (((kc + bK8) * 2) ^ ((row & 7) << 4)));
                    LDSM4(b[nxt][nbk][0], b[nxt][nbk][1], b[nxt][nbk][2], b[nxt][nbk][3], stB + off);
                }
            }
#pragma unroll
            for (int mi = 0; mi < 4; mi++)
#pragma unroll
                for (int ni = 0; ni < 8; ni++)
                    MMA16816(acc[mi][ni], a[cur][mi],
                             b[cur][ni >> 1][(ni & 1) * 2], b[cur][ni >> 1][(ni & 1) * 2 + 1]);
        }
        issue(i + STAGES - 1);
    }

    // ---- epilogue ----
#pragma unroll
    for (int mi = 0; mi < 4; mi++) {
        const int m = row0 + wm * 64 + mi * 16 + (lane >> 2);
#pragma unroll
        for (int ni = 0; ni < 8; ni++) {
            const int col = col0 + wn * 64 + ni * 8 + (lane & 3) * 2;
            float2 v0 = make_float2(acc[mi][ni][0], acc[mi][ni][1]);
            float2 v1 = make_float2(acc[mi][ni][2], acc[mi][ni][3]);
            if (col < Ncut) {
                float c0 = cvec[col], c1 = cvec[col + 1];
                float d00 = v0.x - c0, d01 = v0.y - c1;
                float d10 = v1.x - c0, d11 = v1.y - c1;
                float dd0 = d00 * d00 + d01 * d01;
                float dd1 = d10 * d10 + d11 * d11;
                float q0 = dd0 + __shfl_xor_sync(0xffffffffu, dd0, 1);
                float q1 = dd1 + __shfl_xor_sync(0xffffffffu, dd1, 1);
                if ((lane & 1) == 0) {
                    int g = col >> 2;
                    Pq[(size_t)m * NqW + g] = q0;
                    Pq[(size_t)(m + 8) * NqW + g] = q1;
                }
            } else {
                int sc = col - Ncut;
                if (sc < Ns) {
                    if (bias) {
                        float b0 = bias[sc], b1 = bias[sc + 1];
                        v0.x += b0; v0.y += b1; v1.x += b0; v1.y += b1;
                    }
                    *(float2*)(Cs + (size_t)m * Ns + sc) = v0;
                    *(float2*)(Cs + (size_t)(m + 8) * Ns + sc) = v1;
                }
            }
        }
    }
}

// ---------------- fused cast + row sum of squares (layer-1 input) ----------------
__global__ void castx_rowsq(const float* __restrict__ x, __half* __restrict__ xh,
                            float* __restrict__ rsq, int D) {
    int b = blockIdx.x;
    const float* p = x + (size_t)b * D;
    __half* o = xh + (size_t)b * D;
    float s = 0.f;
    for (int i = threadIdx.x; i < D; i += 256) {
        float v = p[i];
        o[i] = __float2half(v);
        s = fmaf(v, v, s);
    }
    __shared__ float red[256];
    red[threadIdx.x] = s;
    __syncthreads();
    for (int off = 128; off > 0; off >>= 1) {
        if (threadIdx.x < off) red[threadIdx.x] += red[threadIdx.x + off];
        __syncthreads();
    }
    if (threadIdx.x == 0) rsq[b] = red[0];
}

// ---------------- cast: fp32 -> fp16 ----------------
__global__ void castH(const float* __restrict__ src, __half* __restrict__ dst) {
    size_t i = (size_t)blockIdx.x * 256 + threadIdx.x;
    dst[i] = __float2half(src[i]);
}

// ------- fused prep + cast -------
__global__ void prep_cast(const float* __restrict__ mu, const float* __restrict__ v,
                          __half* __restrict__ B1,
                          float* __restrict__ msq, float* __restrict__ c, int D) {
    int n = blockIdx.x;
    const float* mp = mu + (size_t)n * D;
    const float* vp = v + (size_t)n * KLR * D;
    __half* bmu = B1 + ((size_t)(NH * KLR) + n) * D;
    __half* bv  = B1 + (size_t)n * KLR * D;
    float acc[5] = {0.f, 0.f, 0.f, 0.f, 0.f};
    for (int i = threadIdx.x; i < D; i += 256) {
        float m = mp[i];
        bmu[i] = __float2half(m);
        acc[0] = fmaf(m, m, acc[0]);
#pragma unroll
        for (int k = 0; k < KLR; k++) {
            float vv = vp[(size_t)k * D + i];
            bv[(size_t)k * D + i] = __float2half(vv);
            acc[k + 1] = fmaf(m, vv, acc[k + 1]);
        }
    }
    __shared__ float red[256];
    for (int j = 0; j < 5; j++) {
        red[threadIdx.x] = acc[j];
        __syncthreads();
        for (int off = 128; off > 0; off >>= 1) {
            if (threadIdx.x < off) red[threadIdx.x] += red[threadIdx.x + off];
            __syncthreads();
        }
        if (threadIdx.x == 0) {
            if (j == 0) msq[n] = red[0];
            else        c[n * KLR + (j - 1)] = red[0];
        }
        __syncthreads();
    }
}

// ------- fused quad epilogue + shifted fp32 BN partial statistics -------
// 4 independent accumulator pairs break the FADD dependency chain.
__global__ void quad_bnsum(const float* __restrict__ S, const float* __restrict__ Pq,
                           const float* __restrict__ rsq, const float* __restrict__ msq,
                           const float* __restrict__ lam,
                           float* __restrict__ t, float* __restrict__ psum,
                           float* __restrict__ psq, int mode) {
    int n = blockIdx.x * 256 + threadIdx.x;
    int seg = blockIdx.y;
    const int rows = BATCH / NSEG;   // 64
    float lamn = lam[n];
    float msqn = msq[n];
    const float shiftv = mode ? 1.0f : 0.0f;
    float sa[4] = {0.f, 0.f, 0.f, 0.f};
    float qa[4] = {0.f, 0.f, 0.f, 0.f};
    size_t b0 = (size_t)seg * rows;
    for (int r = 0; r < rows; r += 4) {
#pragma unroll
        for (int j = 0; j < 4; j++) {
            size_t b = b0 + r + j;
            size_t idx = b * NH + n;
            float q = lamn * (rsq[b] - 2.f * S[idx] + msqn) + Pq[idx];
            float v = mode ? expf(-q * (1.0f / (float)NH)) : -q;
            t[idx] = v;
            float d = v - shiftv;
            sa[j] += d;
            qa[j] = fmaf(d, d, qa[j]);
        }
    }
    psum[seg * NH + n] = (sa[0] + sa[1]) + (sa[2] + sa[3]);
    psq[seg * NH + n] = (qa[0] + qa[1]) + (qa[2] + qa[3]);
}

// ------- BN finalize: fp64 combine of shifted fp32 partials -------
__global__ void bn_stats(const float* __restrict__ psum, const float* __restrict__ psq,
                         const float* __restrict__ g, const float* __restrict__ be,
                         float* __restrict__ scale, float* __restrict__ shift, int mode) {
    int n = blockIdx.x * 256 + threadIdx.x;
    double s = 0.0, s2 = 0.0;
    for (int i = 0; i < NSEG; i++) { s += (double)psum[i * NH + n]; s2 += (double)psq[i * NH + n]; }
    double md = s * (1.0 / (double)BATCH);                 // E[v - shift]
    double var = s2 * (1.0 / (double)BATCH) - md * md;     // shift-invariant
    double mean = (mode ? 1.0 : 0.0) + md;
    float rstd = (float)(1.0 / sqrt(var + (double)BN_EPS));
    float sc = g[n] * rstd;
    scale[n] = sc;
    shift[n] = be[n] - (float)mean * sc;
}

// ------- BN apply fused with next-layer rowsq -------
__global__ void bn_apply(const float* __restrict__ t, const float* __restrict__ scale,
                         const float* __restrict__ shift,
                         __half* __restrict__ f1, float* __restrict__ rsq,
                         float* o1, float* o2, int relu) {
    int b = blockIdx.x;
    const float* tp = t + (size_t)b * NH;
    __half* fp = f1 + (size_t)b * NH;
    float s = 0.f;
    for (int n = threadIdx.x; n < NH; n += 256) {
        float v = fmaf(tp[n], scale[n], shift[n]);
        if (relu) v = fmaxf(v, 0.f);
        fp[n] = __float2half(v);
        s = fmaf(v, v, s);
        if (o1) o1[(size_t)b * NH + n] = v;
        if (o2) o2[(size_t)b * NH + n] = v;
    }
    if (rsq) {
        __shared__ float red[256];
        red[threadIdx.x] = s;
        __syncthreads();
        for (int off = 128; off > 0; off >>= 1) {
            if (threadIdx.x < off) red[threadIdx.x] += red[threadIdx.x + off];
            __syncthreads();
        }
        if (threadIdx.x == 0) rsq[b] = red[0];
    }
}

// ---------------- host orchestration ----------------
extern "C" void kernel_launch(void* const* d_in, const int* in_sizes, int n_in,
                              void* d_out, int out_size) {
    const float* x    = (const float*)d_in[0];
    const float* mu1  = (const float*)d_in[1];
    const float* lam1 = (const float*)d_in[2];
    const float* v1   = (const float*)d_in[3];
    const float* g1   = (const float*)d_in[4];
    const float* b1   = (const float*)d_in[5];
    const float* mu2  = (const float*)d_in[6];
    const float* lam2 = (const float*)d_in[7];
    const float* v2   = (const float*)d_in[8];
    const float* g2   = (const float*)d_in[9];
    const float* b2   = (const float*)d_in[10];
    const float* Wl   = (const float*)d_in[11];
    const float* bl   = (const float*)d_in[12];

    float *pS, *pPq, *pT, *pR, *pM, *pC, *pScale, *pShift, *pPsum, *pPsq;
    __half *pA1x, *pA1f, *pB1, *pB1l;
    cudaGetSymbolAddress((void**)&pS, g_S);
    cudaGetSymbolAddress((void**)&pPq, g_Pq);
    cudaGetSymbolAddress((void**)&pT, g_t);
    cudaGetSymbolAddress((void**)&pA1x, g_a1x);
    cudaGetSymbolAddress((void**)&pA1f, g_a1f);
    cudaGetSymbolAddress((void**)&pB1, g_b1);
    cudaGetSymbolAddress((void**)&pB1l, g_b1l);
    cudaGetSymbolAddress((void**)&pR, g_rowsq);
    cudaGetSymbolAddress((void**)&pM, g_msq);
    cudaGetSymbolAddress((void**)&pC, g_c);
    cudaGetSymbolAddress((void**)&pScale, g_scale);
    cudaGetSymbolAddress((void**)&pShift, g_shift);
    cudaGetSymbolAddress((void**)&pPsum, g_psum);
    cudaGetSymbolAddress((void**)&pPsq, g_psq);

    cudaFuncSetAttribute(gemm_mma, cudaFuncAttributeMaxDynamicSharedMemorySize, SMEM_TOTAL);

    const size_t LOGITS_SZ = (size_t)BATCH * NCLS;
    const size_t FEAT_SZ   = (size_t)BATCH * NH;
    float* out = (float*)d_out;
    size_t extra = ((size_t)out_size > LOGITS_SZ) ? ((size_t)out_size - LOGITS_SZ) / FEAT_SZ : 0;
    float* f1dst = (extra >= 1) ? out + LOGITS_SZ : nullptr;
    float* f2a   = (extra >= 2) ? out + LOGITS_SZ + FEAT_SZ : nullptr;
    float* f2b   = (extra >= 3) ? out + LOGITS_SZ + 2 * FEAT_SZ : nullptr;

    dim3 bn_grid(NH / 256, NSEG);
    const int Mt = BATCH / 128;
    const int NMERGED = NH * (KLR + 1);
    const int merged_grid = Mt * (NMERGED / 128);

    // ---------- Layer 1 ----------
    castx_rowsq<<<BATCH, 256>>>(x, pA1x, pR, D_IN);
    prep_cast<<<NH, 256>>>(mu1, v1, pB1, pM, pC, D_IN);
    gemm_mma<<<merged_grid, 128, SMEM_TOTAL>>>(pA1x, pB1, pPq, pS, pC, Mt, NH * KLR, NMERGED, NH, NH, D_IN, nullptr);
    quad_bnsum<<<bn_grid, 256>>>(pS, pPq, pR, pM, lam1, pT, pPsum, pPsq, 0);
    bn_stats<<<NH / 256, 256>>>(pPsum, pPsq, g1, b1, pScale, pShift, 0);
    bn_apply<<<BATCH, 256>>>(pT, pScale, pShift, pA1f, pR, f1dst, nullptr, 0);

    // ---------- Layer 2 ----------
    prep_cast<<<NH, 256>>>(mu2, v2, pB1, pM, pC, NH);
    gemm_mma<<<merged_grid, 128, SMEM_TOTAL>>>(pA1f, pB1, pPq, pS, pC, Mt, NH * KLR, NMERGED, NH, NH, NH, nullptr);
    quad_bnsum<<<bn_grid, 256>>>(pS, pPq, pR, pM, lam2, pT, pPsum, pPsq, 1);
    bn_stats<<<NH / 256, 256>>>(pPsum, pPsq, g2, b2, pScale, pShift, 1);
    bn_apply<<<BATCH, 256>>>(pT, pScale, pShift, pA1f, nullptr, f2a, f2b, 1);

    // ---------- Logits ----------
    castH<<<(NCLS * NH) / 256, 256>>>(Wl, pB1l);
    gemm_mma<<<Mt * ((NCLS + 127) / 128), 128, SMEM_TOTAL>>>(pA1f, pB1l, nullptr, out, nullptr, Mt, 0, NCLS, NCLS, 0, NH, bl);
}

// round 12
// speedup vs baseline: 2.0282x; 1.0106x over previous
#include <cuda_runtime.h>
#include <cuda_fp16.h>
#include <cstdint>

// Problem constants
#define BATCH 8192
#define D_IN  1024
#define NH    2048
#define KLR   4
#define NCLS  1000
#define BN_EPS 1e-5f
#define NSEG  256

#define STAGES 3
#define STAGE_BYTES 32768           // A 16KB (128x128B) | B 16KB (128x128B)
#define SMEM_TOTAL (STAGES * STAGE_BYTES)

static __device__ __forceinline__ uint32_t smem_u32(const void* p) {
    uint32_t a;
    asm("{ .reg .u64 t; cvta.to.shared.u64 t, %1; cvt.u32.u64 %0, t; }" : "=r"(a) : "l"(p));
    return a;
}
static __device__ __forceinline__ void cp16(uint32_t dst, const void* src, uint32_t bytes) {
    asm volatile("cp.async.cg.shared.global [%0], [%1], 16, %2;" :: "r"(dst), "l"(src), "r"(bytes) : "memory");
}
#define CP_COMMIT() asm volatile("cp.async.commit_group;" ::: "memory")
#define CP_WAIT(n)  asm volatile("cp.async.wait_group %0;" :: "n"(n) : "memory")
#define LDSM4(r0, r1, r2, r3, a) \
    asm volatile("ldmatrix.sync.aligned.m8n8.x4.shared.b16 {%0,%1,%2,%3}, [%4];" \
        : "=r"(r0), "=r"(r1), "=r"(r2), "=r"(r3) : "r"(a))
#define MMA16816(c, a, b0, b1) \
    asm volatile("mma.sync.aligned.m16n8k16.row.col.f32.f16.f16.f32 " \
        "{%0,%1,%2,%3},{%4,%5,%6,%7},{%8,%9},{%0,%1,%2,%3};" \
        : "+f"((c)[0]), "+f"((c)[1]), "+f"((c)[2]), "+f"((c)[3]) \
        : "r"((a)[0]), "r"((a)[1]), "r"((a)[2]), "r"((a)[3]), "r"(b0), "r"(b1))

// pack 4 floats -> 4 halves (8 bytes)
static __device__ __forceinline__ void store_half4(__half* p, float4 f) {
    __half2* h = (__half2*)p;
    h[0] = __floats2half2_rn(f.x, f.y);
    h[1] = __floats2half2_rn(f.z, f.w);
}

// ---------------- static device scratch ----------------
__device__ float g_S[(size_t)BATCH * NH];
__device__ float g_Pq[(size_t)BATCH * NH];
__device__ float g_t[(size_t)BATCH * NH];
__device__ __align__(1024) __half g_a1x[(size_t)BATCH * D_IN];
__device__ __align__(1024) __half g_a1f[(size_t)BATCH * NH];
__device__ __align__(1024) __half g_b1[(size_t)(NH * KLR + NH) * NH];
__device__ __align__(1024) __half g_b1l[(size_t)NCLS * NH];
__device__ float g_rowsq[BATCH];
__device__ float g_msq[NH];
__device__ float g_c[NH * KLR];
__device__ float g_scale[NH];
__device__ float g_shift[NH];
__device__ float g_psum[NSEG * NH];
__device__ float g_psq[NSEG * NH];

// ===== HMMA fp16 GEMM: 128x128 CTA, 4 warps (2x2), 64x64 warp tile, 2 CTA/SM =====
__global__ void __launch_bounds__(128, 2)
gemm_mma(const __half* __restrict__ A1, const __half* __restrict__ B1,
         float* __restrict__ Pq, float* __restrict__ Cs, const float* __restrict__ cvec,
         int Mt, int Ncut, int Ntot, int Ns, int NqW, int Kd, const float* __restrict__ bias)
{
    extern __shared__ __align__(1024) char smem[];
    const uint32_t sbase = smem_u32(smem);
    const int tid = threadIdx.x;
    const int wid = tid >> 5;
    const int lane = tid & 31;
    const int wm = wid >> 1;
    const int wn = wid & 1;

    const int nt_total = (Ntot + 127) >> 7;
    const int bw0 = 8;
    const int per_band = Mt * bw0;
    const int band = blockIdx.x / per_band;
    const int rem = blockIdx.x % per_band;
    int nb = nt_total - band * bw0; if (nb > bw0) nb = bw0;
    const int mtile = rem / nb;
    const int ntile = band * bw0 + rem % nb;
    const int row0 = mtile * 128;
    const int col0 = ntile * 128;
    const int nk = Kd >> 6;

    float acc[4][8][4];
#pragma unroll
    for (int i = 0; i < 4; i++)
#pragma unroll
        for (int j = 0; j < 8; j++)
#pragma unroll
            for (int r = 0; r < 4; r++) acc[i][j][r] = 0.f;

    const int aRow = wm * 64 + (lane & 15);
    const int aK8 = (lane >> 4) * 8;
    const int bRow = wn * 64 + (lane & 7) + ((lane >> 4) & 1) * 8;
    const int bK8 = ((lane >> 3) & 1) * 8;

    auto issue = [&](int i) {
        if (i < nk) {
            const int s = i % STAGES;
            const uint32_t stA = sbase + s * STAGE_BYTES;
            const uint32_t stB = stA + 16384;
            const __half* Ab = A1 + (size_t)row0 * Kd + (i << 6);
            const __half* Bb = B1 + (i << 6);
#pragma unroll
            for (int it = 0; it < 8; it++) {
                int id = it * 128 + tid;
                int row = id >> 3, c = id & 7;
                uint32_t off = (uint32_t)(row * 128 + ((c * 16) ^ ((row & 7) << 4)));
                cp16(stA + off, Ab + (size_t)row * Kd + c * 8, 16);
            }
#pragma unroll
            for (int it = 0; it < 8; it++) {
                int id = it * 128 + tid;
                int row = id >> 3, c = id & 7;
                int gn = col0 + row;
                uint32_t bytes = (gn < Ntot) ? 16u : 0u;
                if (gn >= Ntot) gn = col0;
                uint32_t off = (uint32_t)(row * 128 + ((c * 16) ^ ((row & 7) << 4)));
                cp16(stB + off, Bb + (size_t)gn * Kd + c * 8, bytes);
            }
        }
        CP_COMMIT();
    };

#pragma unroll
    for (int i = 0; i < STAGES - 1; i++) issue(i);

    for (int i = 0; i < nk; i++) {
        CP_WAIT(STAGES - 2);
        __syncthreads();
        const int s = i % STAGES;
        const uint32_t stA = sbase + s * STAGE_BYTES;
        const uint32_t stB = stA + 16384;

        uint32_t a[2][4][4], b[2][4][4];
#pragma unroll
        for (int mi = 0; mi < 4; mi++) {
            int row = aRow + mi * 16;
            uint32_t off = (uint32_t)(row * 128 + ((aK8 * 2) ^ ((row & 7) << 4)));
            LDSM4(a[0][mi][0], a[0][mi][1], a[0][mi][2], a[0][mi][3], stA + off);
        }
#pragma unroll
        for (int nbk = 0; nbk < 4; nbk++) {
            int row = bRow + nbk * 16;
            uint32_t off = (uint32_t)(row * 128 + ((bK8 * 2) ^ ((row & 7) << 4)));
            LDSM4(b[0][nbk][0], b[0][nbk][1], b[0][nbk][2], b[0][nbk][3], stB + off);
        }

#pragma unroll
        for (int ks = 0; ks < 4; ks++) {
            const int cur = ks & 1;
            const int nxt = cur ^ 1;
            if (ks < 3) {
                const int kc = (ks + 1) * 16;
#pragma unroll
                for (int mi = 0; mi < 4; mi++) {
                    int row = aRow + mi * 16;
                    uint32_t off = (uint32_t)(row * 128 + (((kc + aK8) * 2) ^ ((row & 7) << 4)));
                    LDSM4(a[nxt][mi][0], a[nxt][mi][1], a[nxt][mi][2], a[nxt][mi][3], stA + off);
                }
#pragma unroll
                for (int nbk = 0; nbk < 4; nbk++) {
                    int row = bRow + nbk * 16;
                    uint32_t off = (uint32_t)(row * 128 + (((kc + bK8) * 2) ^ ((row & 7) << 4)));
                    LDSM4(b[nxt][nbk][0], b[nxt][nbk][1], b[nxt][nbk][2], b[nxt][nbk][3], stB + off);
                }
            }
#pragma unroll
            for (int mi = 0; mi < 4; mi++)
#pragma unroll
                for (int ni = 0; ni < 8; ni++)
                    MMA16816(acc[mi][ni], a[cur][mi],
                             b[cur][ni >> 1][(ni & 1) * 2], b[cur][ni >> 1][(ni & 1) * 2 + 1]);
        }
        issue(i + STAGES - 1);
    }

    // ---- epilogue ----
#pragma unroll
    for (int mi = 0; mi < 4; mi++) {
        const int m = row0 + wm * 64 + mi * 16 + (lane >> 2);
#pragma unroll
        for (int ni = 0; ni < 8; ni++) {
            const int col = col0 + wn * 64 + ni * 8 + (lane & 3) * 2;
            float2 v0 = make_float2(acc[mi][ni][0], acc[mi][ni][1]);
            float2 v1 = make_float2(acc[mi][ni][2], acc[mi][ni][3]);
            if (col < Ncut) {
                float c0 = cvec[col], c1 = cvec[col + 1];
                float d00 = v0.x - c0, d01 = v0.y - c1;
                float d10 = v1.x - c0, d11 = v1.y - c1;
                float dd0 = d00 * d00 + d01 * d01;
                float dd1 = d10 * d10 + d11 * d11;
                float q0 = dd0 + __shfl_xor_sync(0xffffffffu, dd0, 1);
                float q1 = dd1 + __shfl_xor_sync(0xffffffffu, dd1, 1);
                if ((lane & 1) == 0) {
                    int g = col >> 2;
                    Pq[(size_t)m * NqW + g] = q0;
                    Pq[(size_t)(m + 8) * NqW + g] = q1;
                }
            } else {
                int sc = col - Ncut;
                if (sc < Ns) {
                    if (bias) {
                        float b0 = bias[sc], b1 = bias[sc + 1];
                        v0.x += b0; v0.y += b1; v1.x += b0; v1.y += b1;
                    }
                    *(float2*)(Cs + (size_t)m * Ns + sc) = v0;
                    *(float2*)(Cs + (size_t)(m + 8) * Ns + sc) = v1;
                }
            }
        }
    }
}

// ------- fused cast + rowsq, float4/half2 vectorized -------
__global__ void castx_rowsq(const float* __restrict__ x, __half* __restrict__ xh,
                            float* __restrict__ rsq, int D) {
    int b = blockIdx.x;
    const float* p = x + (size_t)b * D;
    __half* o = xh + (size_t)b * D;
    float s = 0.f;
    for (int i = threadIdx.x * 4; i < D; i += 1024) {
        float4 v = *(const float4*)(p + i);
        store_half4(o + i, v);
        s = fmaf(v.x, v.x, s); s = fmaf(v.y, v.y, s);
        s = fmaf(v.z, v.z, s); s = fmaf(v.w, v.w, s);
    }
    __shared__ float red[256];
    red[threadIdx.x] = s;
    __syncthreads();
    for (int off = 128; off > 0; off >>= 1) {
        if (threadIdx.x < off) red[threadIdx.x] += red[threadIdx.x + off];
        __syncthreads();
    }
    if (threadIdx.x == 0) rsq[b] = red[0];
}

// ---------------- cast: fp32 -> fp16 (vectorized) ----------------
__global__ void castH(const float* __restrict__ src, __half* __restrict__ dst) {
    size_t i = ((size_t)blockIdx.x * 256 + threadIdx.x) * 4;
    float4 v = *(const float4*)(src + i);
    store_half4(dst + i, v);
}

// ------- fused prep + cast (float4 vectorized) -------
__global__ void prep_cast(const float* __restrict__ mu, const float* __restrict__ v,
                          __half* __restrict__ B1,
                          float* __restrict__ msq, float* __restrict__ c, int D) {
    int n = blockIdx.x;
    const float* mp = mu + (size_t)n * D;
    const float* vp = v + (size_t)n * KLR * D;
    __half* bmu = B1 + ((size_t)(NH * KLR) + n) * D;
    __half* bv  = B1 + (size_t)n * KLR * D;
    float acc[5] = {0.f, 0.f, 0.f, 0.f, 0.f};
    for (int i = threadIdx.x * 4; i < D; i += 1024) {
        float4 m = *(const float4*)(mp + i);
        store_half4(bmu + i, m);
        acc[0] = fmaf(m.x, m.x, fmaf(m.y, m.y, fmaf(m.z, m.z, fmaf(m.w, m.w, acc[0]))));
#pragma unroll
        for (int k = 0; k < KLR; k++) {
            float4 vv = *(const float4*)(vp + (size_t)k * D + i);
            store_half4(bv + (size_t)k * D + i, vv);
            acc[k + 1] = fmaf(m.x, vv.x, fmaf(m.y, vv.y, fmaf(m.z, vv.z, fmaf(m.w, vv.w, acc[k + 1]))));
        }
    }
    __shared__ float red[256];
    for (int j = 0; j < 5; j++) {
        red[threadIdx.x] = acc[j];
        __syncthreads();
        for (int off = 128; off > 0; off >>= 1) {
            if (threadIdx.x < off) red[threadIdx.x] += red[threadIdx.x + off];
            __syncthreads();
        }
        if (threadIdx.x == 0) {
            if (j == 0) msq[n] = red[0];
            else        c[n * KLR + (j - 1)] = red[0];
        }
        __syncthreads();
    }
}

// ------- fused quad epilogue + shifted fp32 BN stats, 4 columns per thread -------
__global__ void quad_bnsum(const float* __restrict__ S, const float* __restrict__ Pq,
                           const float* __restrict__ rsq, const float* __restrict__ msq,
                           const float* __restrict__ lam,
                           float* __restrict__ t, float* __restrict__ psum,
                           float* __restrict__ psq, int mode) {
    int n0 = (blockIdx.x * 256 + threadIdx.x) * 4;
    int seg = blockIdx.y;
    const int rows = BATCH / NSEG;   // 32
    float4 lamv = *(const float4*)(lam + n0);
    float4 msqv = *(const float4*)(msq + n0);
    const float shiftv = mode ? 1.0f : 0.0f;
    float sa[4] = {0.f, 0.f, 0.f, 0.f};
    float qa[4] = {0.f, 0.f, 0.f, 0.f};
    size_t b0 = (size_t)seg * rows;
    for (int r = 0; r < rows; r++) {
        size_t b = b0 + r;
        size_t idx = b * NH + n0;
        float rs = rsq[b];
        float4 sv = *(const float4*)(S + idx);
        float4 pv = *(const float4*)(Pq + idx);
        float q0 = lamv.x * (rs - 2.f * sv.x + msqv.x) + pv.x;
        float q1 = lamv.y * (rs - 2.f * sv.y + msqv.y) + pv.y;
        float q2 = lamv.z * (rs - 2.f * sv.z + msqv.z) + pv.z;
        float q3 = lamv.w * (rs - 2.f * sv.w + msqv.w) + pv.w;
        float4 vv;
        if (mode) {
            vv.x = expf(-q0 * (1.0f / (float)NH));
            vv.y = expf(-q1 * (1.0f / (float)NH));
            vv.z = expf(-q2 * (1.0f / (float)NH));
            vv.w = expf(-q3 * (1.0f / (float)NH));
        } else {
            vv.x = -q0; vv.y = -q1; vv.z = -q2; vv.w = -q3;
        }
        *(float4*)(t + idx) = vv;
        float d0 = vv.x - shiftv, d1 = vv.y - shiftv, d2 = vv.z - shiftv, d3 = vv.w - shiftv;
        sa[0] += d0; sa[1] += d1; sa[2] += d2; sa[3] += d3;
        qa[0] = fmaf(d0, d0, qa[0]); qa[1] = fmaf(d1, d1, qa[1]);
        qa[2] = fmaf(d2, d2, qa[2]); qa[3] = fmaf(d3, d3, qa[3]);
    }
    *(float4*)(psum + (size_t)seg * NH + n0) = make_float4(sa[0], sa[1], sa[2], sa[3]);
    *(float4*)(psq + (size_t)seg * NH + n0) = make_float4(qa[0], qa[1], qa[2], qa[3]);
}

// ------- BN finalize: fp64 combine of shifted fp32 partials -------
__global__ void bn_stats(const float* __restrict__ psum, const float* __restrict__ psq,
                         const float* __restrict__ g, const float* __restrict__ be,
                         float* __restrict__ scale, float* __restrict__ shift, int mode) {
    int n = blockIdx.x * 256 + threadIdx.x;
    double s = 0.0, s2 = 0.0;
    for (int i = 0; i < NSEG; i++) { s += (double)psum[i * NH + n]; s2 += (double)psq[i * NH + n]; }
    double md = s * (1.0 / (double)BATCH);
    double var = s2 * (1.0 / (double)BATCH) - md * md;
    double mean = (mode ? 1.0 : 0.0) + md;
    float rstd = (float)(1.0 / sqrt(var + (double)BN_EPS));
    float sc = g[n] * rstd;
    scale[n] = sc;
    shift[n] = be[n] - (float)mean * sc;
}

// ------- BN apply (vectorized) fused with next-layer rowsq -------
__global__ void bn_apply(const float* __restrict__ t, const float* __restrict__ scale,
                         const float* __restrict__ shift,
                         __half* __restrict__ f1, float* __restrict__ rsq,
                         float* o1, float* o2, int relu) {
    int b = blockIdx.x;
    const float* tp = t + (size_t)b * NH;
    __half* fp = f1 + (size_t)b * NH;
    float s = 0.f;
    for (int n = threadIdx.x * 4; n < NH; n += 1024) {
        float4 tv = *(const float4*)(tp + n);
        float4 sc = *(const float4*)(scale + n);
        float4 sh = *(const float4*)(shift + n);
        float4 vv;
        vv.x = fmaf(tv.x, sc.x, sh.x);
        vv.y = fmaf(tv.y, sc.y, sh.y);
        vv.z = fmaf(tv.z, sc.z, sh.z);
        vv.w = fmaf(tv.w, sc.w, sh.w);
        if (relu) {
            vv.x = fmaxf(vv.x, 0.f); vv.y = fmaxf(vv.y, 0.f);
            vv.z = fmaxf(vv.z, 0.f); vv.w = fmaxf(vv.w, 0.f);
        }
        store_half4(fp + n, vv);
        s = fmaf(vv.x, vv.x, s); s = fmaf(vv.y, vv.y, s);
        s = fmaf(vv.z, vv.z, s); s = fmaf(vv.w, vv.w, s);
        if (o1) *(float4*)(o1 + (size_t)b * NH + n) = vv;
        if (o2) *(float4*)(o2 + (size_t)b * NH + n) = vv;
    }
    if (rsq) {
        __shared__ float red[256];
        red[threadIdx.x] = s;
        __syncthreads();
        for (int off = 128; off > 0; off >>= 1) {
            if (threadIdx.x < off) red[threadIdx.x] += red[threadIdx.x + off];
            __syncthreads();
        }
        if (threadIdx.x == 0) rsq[b] = red[0];
    }
}

// ---------------- host orchestration ----------------
extern "C" void kernel_launch(void* const* d_in, const int* in_sizes, int n_in,
                              void* d_out, int out_size) {
    const float* x    = (const float*)d_in[0];
    const float* mu1  = (const float*)d_in[1];
    const float* lam1 = (const float*)d_in[2];
    const float* v1   = (const float*)d_in[3];
    const float* g1   = (const float*)d_in[4];
    const float* b1   = (const float*)d_in[5];
    const float* mu2  = (const float*)d_in[6];
    const float* lam2 = (const float*)d_in[7];
    const float* v2   = (const float*)d_in[8];
    const float* g2   = (const float*)d_in[9];
    const float* b2   = (const float*)d_in[10];
    const float* Wl   = (const float*)d_in[11];
    const float* bl   = (const float*)d_in[12];

    float *pS, *pPq, *pT, *pR, *pM, *pC, *pScale, *pShift, *pPsum, *pPsq;
    __half *pA1x, *pA1f, *pB1, *pB1l;
    cudaGetSymbolAddress((void**)&pS, g_S);
    cudaGetSymbolAddress((void**)&pPq, g_Pq);
    cudaGetSymbolAddress((void**)&pT, g_t);
    cudaGetSymbolAddress((void**)&pA1x, g_a1x);
    cudaGetSymbolAddress((void**)&pA1f, g_a1f);
    cudaGetSymbolAddress((void**)&pB1, g_b1);
    cudaGetSymbolAddress((void**)&pB1l, g_b1l);
    cudaGetSymbolAddress((void**)&pR, g_rowsq);
    cudaGetSymbolAddress((void**)&pM, g_msq);
    cudaGetSymbolAddress((void**)&pC, g_c);
    cudaGetSymbolAddress((void**)&pScale, g_scale);
    cudaGetSymbolAddress((void**)&pShift, g_shift);
    cudaGetSymbolAddress((void**)&pPsum, g_psum);
    cudaGetSymbolAddress((void**)&pPsq, g_psq);

    cudaFuncSetAttribute(gemm_mma, cudaFuncAttributeMaxDynamicSharedMemorySize, SMEM_TOTAL);

    const size_t LOGITS_SZ = (size_t)BATCH * NCLS;
    const size_t FEAT_SZ   = (size_t)BATCH * NH;
    float* out = (float*)d_out;
    size_t extra = ((size_t)out_size > LOGITS_SZ) ? ((size_t)out_size - LOGITS_SZ) / FEAT_SZ : 0;
    float* f1dst = (extra >= 1) ? out + LOGITS_SZ : nullptr;
    float* f2a   = (extra >= 2) ? out + LOGITS_SZ + FEAT_SZ : nullptr;
    float* f2b   = (extra >= 3) ? out + LOGITS_SZ + 2 * FEAT_SZ : nullptr;

    dim3 bn_grid(NH / 1024, NSEG);       // (2, 256)
    const int Mt = BATCH / 128;
    const int NMERGED = NH * (KLR + 1);
    const int merged_grid = Mt * (NMERGED / 128);

    // ---------- Layer 1 ----------
    castx_rowsq<<<BATCH, 256>>>(x, pA1x, pR, D_IN);
    prep_cast<<<NH, 256>>>(mu1, v1, pB1, pM, pC, D_IN);
    gemm_mma<<<merged_grid, 128, SMEM_TOTAL>>>(pA1x, pB1, pPq, pS, pC, Mt, NH * KLR, NMERGED, NH, NH, D_IN, nullptr);
    quad_bnsum<<<bn_grid, 256>>>(pS, pPq, pR, pM, lam1, pT, pPsum, pPsq, 0);
    bn_stats<<<NH / 256, 256>>>(pPsum, pPsq, g1, b1, pScale, pShift, 0);
    bn_apply<<<BATCH, 256>>>(pT, pScale, pShift, pA1f, pR, f1dst, nullptr, 0);

    // ---------- Layer 2 ----------
    prep_cast<<<NH, 256>>>(mu2, v2, pB1, pM, pC, NH);
    gemm_mma<<<merged_grid, 128, SMEM_TOTAL>>>(pA1f, pB1, pPq, pS, pC, Mt, NH * KLR, NMERGED, NH, NH, NH, nullptr);
    quad_bnsum<<<bn_grid, 256>>>(pS, pPq, pR, pM, lam2, pT, pPsum, pPsq, 1);
    bn_stats<<<NH / 256, 256>>>(pPsum, pPsq, g2, b2, pScale, pShift, 1);
    bn_apply<<<BATCH, 256>>>(pT, pScale, pShift, pA1f, nullptr, f2a, f2b, 1);

    // ---------- Logits ----------
    castH<<<(NCLS * NH) / 1024, 256>>>(Wl, pB1l);
    gemm_mma<<<Mt * ((NCLS + 127) / 128), 128, SMEM_TOTAL>>>(pA1f, pB1l, nullptr, out, nullptr, Mt, 0, NCLS, NCLS, 0, NH, bl);
}